// round 10
// baseline (speedup 1.0000x reference)
#include <cuda_runtime.h>
#include <cuda_bf16.h>
#include <cstdint>

#define BATCH 32
#define IN_F  784
#define H1    1024
#define H2    1024
#define NC    10
#define EPSV  0.1f
#define NROWS (BATCH * NC)   // 320
#define MROWS1 384           // padded rows for final GEMM (3 x 128)
#define NT_TILES 7           // 7*128 = 896 >= 784
#define SASTRIDE 40          // halves per smem row (80B; conflict-free ldmatrix)
#define STAGEB (128 * SASTRIDE * 2)   // 10240 bytes per stage per matrix
#define NIBLK 8              // i-blocks in k_nu1f

// ---------------- scratch (device globals) ----------------------------------
__device__ float g_r1[H1];
__device__ float g_nom1[BATCH * H1];
__device__ float g_d1[BATCH * H1];
__device__ float g_l1m[BATCH * H1];
__device__ float g_E2[BATCH * H2];
__device__ float g_d2[BATCH * H2];
__device__ float g_l2m[BATCH * H2];
__device__ float g_nu2[NROWS * H2];
__device__ float g_term[NROWS];
__device__ __nv_bfloat16 g_nu1fb[MROWS1 * H1];    // rows 320..383 zero
__device__ __nv_bfloat16 g_W1T[H1 * H1];          // W1^T bf16; rows >=784 zero
__device__ __nv_bfloat16 g_Ab[(size_t)BATCH * H2 * H1];  // W2 * d1[b] (64MB)
__device__ float g_Efp[NT_TILES][NROWS];
__device__ float g_afp[NIBLK][NROWS];
__device__ float g_crp[NIBLK][NROWS];

// ---------------- helpers ----------------------------------------------------
__device__ __forceinline__ uint32_t smem_u32(const void* p) {
    uint32_t a;
    asm("{ .reg .u64 t; cvta.to.shared.u64 t, %1; cvt.u32.u64 %0, t; }" : "=r"(a) : "l"(p));
    return a;
}
__device__ __forceinline__ void cp_async16(uint32_t saddr, const void* gaddr) {
    asm volatile("cp.async.cg.shared.global [%0], [%1], 16;" :: "r"(saddr), "l"(gaddr));
}
__device__ __forceinline__ void cp_commit() {
    asm volatile("cp.async.commit_group;" ::: "memory");
}
template <int N>
__device__ __forceinline__ void cp_wait() {
    asm volatile("cp.async.wait_group %0;" :: "n"(N) : "memory");
}
__device__ __forceinline__ void ldsm_x4(uint32_t& r0, uint32_t& r1, uint32_t& r2,
                                        uint32_t& r3, uint32_t addr) {
    asm volatile("ldmatrix.sync.aligned.m8n8.x4.shared.b16 {%0,%1,%2,%3}, [%4];"
                 : "=r"(r0), "=r"(r1), "=r"(r2), "=r"(r3) : "r"(addr));
}
__device__ __forceinline__ void mma16816(float* c, const uint32_t* a, uint32_t b0,
                                         uint32_t b1) {
    asm volatile(
        "mma.sync.aligned.m16n8k16.row.col.f32.bf16.bf16.f32 "
        "{%0,%1,%2,%3}, {%4,%5,%6,%7}, {%8,%9}, {%0,%1,%2,%3};"
        : "+f"(c[0]), "+f"(c[1]), "+f"(c[2]), "+f"(c[3])
        : "r"(a[0]), "r"(a[1]), "r"(a[2]), "r"(a[3]), "r"(b0), "r"(b1));
}
__device__ __forceinline__ float warp_sum(float v) {
    #pragma unroll
    for (int o = 16; o > 0; o >>= 1) v += __shfl_xor_sync(0xFFFFFFFFu, v, o);
    return v;
}
__device__ __forceinline__ void relu_coeffs(float zl, float zu, float& d, float& lm) {
    if (zl >= 0.f)      { d = 1.f; lm = 0.f; }
    else if (zu <= 0.f) { d = 0.f; lm = 0.f; }
    else                { d = zu / (zu - zl); lm = zl; }
}

// ---------------- K0: r1 ------------------------------------------------------
__global__ void k_r1(const float* __restrict__ W1) {
    int gw = (blockIdx.x * blockDim.x + threadIdx.x) >> 5, lane = threadIdx.x & 31;
    if (gw >= H1) return;
    const float* row = W1 + gw * IN_F;
    float s = 0.f;
    for (int k = lane; k < IN_F; k += 32) s += fabsf(row[k]);
    s = warp_sum(s);
    if (lane == 0) g_r1[gw] = EPSV * s;
}

// ---------------- W1 transpose -> bf16 ---------------------------------------
__global__ void k_w1t(const float* __restrict__ W1) {
    __shared__ float tile[32][33];
    int n0 = blockIdx.x * 32, i0 = blockIdx.y * 32;
    int tx = threadIdx.x, ty = threadIdx.y;      // 32 x 8
    #pragma unroll
    for (int r = 0; r < 4; r++) {
        int i = i0 + ty + 8 * r, n = n0 + tx;
        tile[ty + 8 * r][tx] = (n < IN_F) ? W1[i * IN_F + n] : 0.f;
    }
    __syncthreads();
    #pragma unroll
    for (int r = 0; r < 4; r++) {
        int n = n0 + ty + 8 * r;
        if (n < IN_F)
            g_W1T[(size_t)n * H1 + i0 + tx] = __float2bfloat16(tile[tx][ty + 8 * r]);
    }
}

// ---------------- zero pads ---------------------------------------------------
__global__ void k_zero() {
    int idx = blockIdx.x * 256 + threadIdx.x;       // 480*256 = 122880
    uint32_t* w = (uint32_t*)g_W1T;
    w[IN_F * (H1 / 2) + idx] = 0u;                  // W1T rows 784..1023
    if (idx < (MROWS1 - NROWS) * (H1 / 2)) {        // 32768
        uint32_t* nb = (uint32_t*)g_nu1fb;
        nb[NROWS * (H1 / 2) + idx] = 0u;            // nu1fb rows 320..383
    }
}

// ---------------- K1: layer-1 bounds ------------------------------------------
__global__ void k_layer1(const float* __restrict__ x, const float* __restrict__ W1,
                         const float* __restrict__ b1) {
    int gw = (blockIdx.x * blockDim.x + threadIdx.x) >> 5, lane = threadIdx.x & 31;
    int b = gw >> 10, j = gw & (H1 - 1);
    const float* xr = x + b * IN_F;
    const float* wr = W1 + j * IN_F;
    float s = 0.f;
    for (int k = lane; k < IN_F; k += 32) s += xr[k] * wr[k];
    s = warp_sum(s);
    if (lane == 0) {
        float nom = s + b1[j], r = g_r1[j], d, lm;
        relu_coeffs(nom - r, nom + r, d, lm);
        g_nom1[gw] = nom; g_d1[gw] = d; g_l1m[gw] = lm;
    }
}

// ---------------- A precompute: g_Ab = bf16(W2 * d1[b]) -----------------------
__global__ void k_scaleA(const float* __restrict__ W2) {
    size_t idx = ((size_t)blockIdx.x * 256 + threadIdx.x) * 8;    // 32M elems
    int b = (int)(idx >> 20);
    int i = (int)(idx & 1023);
    size_t wo = idx & 0xFFFFFu;
    float4 w0 = *(const float4*)(W2 + wo);
    float4 w1 = *(const float4*)(W2 + wo + 4);
    const float* dp = g_d1 + b * H1 + i;
    float4 e0 = *(const float4*)dp;
    float4 e1 = *(const float4*)(dp + 4);
    __nv_bfloat162 p0 = __floats2bfloat162_rn(w0.x * e0.x, w0.y * e0.y);
    __nv_bfloat162 p1 = __floats2bfloat162_rn(w0.z * e0.z, w0.w * e0.w);
    __nv_bfloat162 p2 = __floats2bfloat162_rn(w1.x * e1.x, w1.y * e1.y);
    __nv_bfloat162 p3 = __floats2bfloat162_rn(w1.z * e1.z, w1.w * e1.w);
    uint4 o;
    o.x = *(uint32_t*)&p0; o.y = *(uint32_t*)&p1;
    o.z = *(uint32_t*)&p2; o.w = *(uint32_t*)&p3;
    *(uint4*)(g_Ab + idx) = o;
}

// ---------------- tensor-core abs-row-sum GEMM --------------------------------
// 128 threads, 2x2 warps, warp tile m64n64, BM=BN=128, 4-stage pipeline.
// RAW rowsum: Eout[b*H2 + blockIdx.y*chunkStride + row] = sum_n |sum_i A[row,i]*B[n,i]|
__global__ void __launch_bounds__(128) k_absgemm_mma(const __nv_bfloat16* __restrict__ Abase,
                                                     float* __restrict__ Eout,
                                                     int rowlimit, int ntPerCta,
                                                     int chunkStride) {
    extern __shared__ char dsm[];
    __nv_bfloat16* sAp = (__nv_bfloat16*)dsm;
    __nv_bfloat16* sBp = sAp + 4 * 128 * SASTRIDE;
    float* sred = (float*)(sBp + 4 * 128 * SASTRIDE);   // [128][2]

    const int tid = threadIdx.x, lane = tid & 31, wid = tid >> 5;
    const int warp_m = wid & 1, warp_n = wid >> 1;       // 2 x 2
    const int mtile = blockIdx.x, b = blockIdx.z;
    const int ntBase = blockIdx.y * ntPerCta;
    const __nv_bfloat16* A = Abase + ((size_t)b * H2 + mtile * 128) * H1;
    const __nv_bfloat16* B = g_W1T;

    const int aRow  = warp_m * 64 + (lane & 7) + ((lane >> 3) & 1) * 8;
    const int aColH = (lane >> 4) * 8;
    const int bRow  = warp_n * 64 + (lane & 7) + (lane >> 4) * 8;
    const int bColH = ((lane >> 3) & 1) * 8;

    const uint32_t sA0 = smem_u32(sAp);
    const uint32_t sB0 = smem_u32(sBp);

    auto copy_stage = [&](int g, int buf) {
        int kt = g & 31, nt = ntBase + (g >> 5);
        int k0 = kt * 32;
        uint32_t Ao = sA0 + (uint32_t)buf * STAGEB;
        uint32_t Bo = sB0 + (uint32_t)buf * STAGEB;
        #pragma unroll
        for (int q = 0; q < 4; q++) {
            cp_async16(Ao + (tid * SASTRIDE + q * 8) * 2,
                       A + (size_t)tid * H1 + k0 + q * 8);
            cp_async16(Bo + (tid * SASTRIDE + q * 8) * 2,
                       B + (size_t)(nt * 128 + tid) * H1 + k0 + q * 8);
        }
    };

    const int total = ntPerCta * 32;
    copy_stage(0, 0); cp_commit();
    copy_stage(1, 1); cp_commit();
    copy_stage(2, 2); cp_commit();

    float rs[4][2];
    #pragma unroll
    for (int mi = 0; mi < 4; mi++) { rs[mi][0] = 0.f; rs[mi][1] = 0.f; }
    float acc[4][8][4];
    #pragma unroll
    for (int mi = 0; mi < 4; mi++)
        #pragma unroll
        for (int ni = 0; ni < 8; ni++)
            #pragma unroll
            for (int e = 0; e < 4; e++) acc[mi][ni][e] = 0.f;

    for (int g = 0; g < total; g++) {
        cp_wait<2>();
        __syncthreads();
        if (g + 3 < total) copy_stage(g + 3, (g + 3) & 3);
        cp_commit();

        int buf = g & 3;
        uint32_t aBase = sA0 + buf * STAGEB;
        uint32_t bBase = sB0 + buf * STAGEB;
        #pragma unroll
        for (int ks = 0; ks < 2; ks++) {
            uint32_t af[4][4];
            #pragma unroll
            for (int mi = 0; mi < 4; mi++)
                ldsm_x4(af[mi][0], af[mi][1], af[mi][2], af[mi][3],
                        aBase + ((aRow + mi * 16) * SASTRIDE + ks * 16 + aColH) * 2);
            uint32_t bf[4][4];
            #pragma unroll
            for (int np = 0; np < 4; np++)
                ldsm_x4(bf[np][0], bf[np][1], bf[np][2], bf[np][3],
                        bBase + ((bRow + np * 16) * SASTRIDE + ks * 16 + bColH) * 2);
            #pragma unroll
            for (int mi = 0; mi < 4; mi++)
                #pragma unroll
                for (int ni = 0; ni < 8; ni++)
                    mma16816(acc[mi][ni], af[mi],
                             bf[ni >> 1][(ni & 1) * 2], bf[ni >> 1][(ni & 1) * 2 + 1]);
        }

        if ((g & 31) == 31) {
            #pragma unroll
            for (int mi = 0; mi < 4; mi++)
                #pragma unroll
                for (int ni = 0; ni < 8; ni++) {
                    rs[mi][0] += fabsf(acc[mi][ni][0]) + fabsf(acc[mi][ni][1]);
                    rs[mi][1] += fabsf(acc[mi][ni][2]) + fabsf(acc[mi][ni][3]);
                    acc[mi][ni][0] = 0.f; acc[mi][ni][1] = 0.f;
                    acc[mi][ni][2] = 0.f; acc[mi][ni][3] = 0.f;
                }
        }
    }

    // quad reduce, then across 2 n-warps via smem
    #pragma unroll
    for (int mi = 0; mi < 4; mi++)
        #pragma unroll
        for (int h = 0; h < 2; h++) {
            float v = rs[mi][h];
            v += __shfl_xor_sync(0xFFFFFFFFu, v, 1);
            v += __shfl_xor_sync(0xFFFFFFFFu, v, 2);
            if ((lane & 3) == 0)
                sred[(warp_m * 64 + mi * 16 + (lane >> 2) + h * 8) * 2 + warp_n] = v;
        }
    __syncthreads();
    {
        float s = sred[tid * 2 + 0] + sred[tid * 2 + 1];
        int grow = mtile * 128 + tid;
        if (grow < rowlimit)
            Eout[(size_t)b * H2 + (size_t)blockIdx.y * chunkStride + grow] = s;
    }
}

// ---------------- K3: layer-2 bounds (reads bf16 g_Ab) -------------------------
__global__ void k_layer2(const float* __restrict__ b2) {
    int gw = (blockIdx.x * blockDim.x + threadIdx.x) >> 5, lane = threadIdx.x & 31;
    int b = gw >> 10, j = gw & (H2 - 1);
    const __nv_bfloat162* ab = (const __nv_bfloat162*)(g_Ab + ((size_t)b * H2 + j) * H1);
    const float2* nom2 = (const float2*)(g_nom1 + b * H1);
    const float2* lm2  = (const float2*)(g_l1m + b * H1);
    float s1 = 0.f, s2 = 0.f, s3 = 0.f;
    for (int i = lane; i < H1 / 2; i += 32) {
        float2 nu = __bfloat1622float2(ab[i]);
        float2 nm = nom2[i];
        float2 lm = lm2[i];
        s1 += nu.x * nm.x + nu.y * nm.y;
        s2 += fmaxf(-nu.x, 0.f) * lm.x + fmaxf(-nu.y, 0.f) * lm.y;
        s3 += fmaxf(nu.x, 0.f) * lm.x + fmaxf(nu.y, 0.f) * lm.y;
    }
    s1 = warp_sum(s1); s2 = warp_sum(s2); s3 = warp_sum(s3);
    if (lane == 0) {
        float A = s1 + b2[j];
        float E = EPSV * g_E2[gw];
        float d, lm;
        relu_coeffs(A - E + s2, A + E - s3, d, lm);
        g_d2[gw] = d; g_l2m[gw] = lm;
    }
}

// ---------------- K4: nu2 + bias/cross ----------------------------------------
__global__ void k_nu2(const float* __restrict__ W3, const float* __restrict__ b2,
                      const float* __restrict__ b3, const int* __restrict__ y) {
    __shared__ float sAq[256], sBq[256];
    int r = blockIdx.x, b = r / NC, j = r % NC;
    int yb = y[b];
    const float* wy = W3 + (size_t)yb * H2;
    const float* wj = W3 + (size_t)j * H2;
    const float* d2r = g_d2 + b * H2;
    const float* lmr = g_l2m + b * H2;
    float sa = 0.f, sbv = 0.f;
    for (int t = threadIdx.x; t < H2; t += 256) {
        float nu = (wy[t] - wj[t]) * d2r[t];
        g_nu2[(size_t)r * H2 + t] = nu;
        sa += fmaxf(-nu, 0.f) * lmr[t];
        sbv += nu * b2[t];
    }
    sAq[threadIdx.x] = sa; sBq[threadIdx.x] = sbv;
    __syncthreads();
    for (int o = 128; o > 0; o >>= 1) {
        if (threadIdx.x < o) {
            sAq[threadIdx.x] += sAq[threadIdx.x + o];
            sBq[threadIdx.x] += sBq[threadIdx.x + o];
        }
        __syncthreads();
    }
    if (threadIdx.x == 0) g_term[r] = (b3[yb] - b3[j]) + sBq[0] + sAq[0];
}

// ---------------- K5: nu1f = nu2 @ g_Ab[b]; fused final dots -------------------
__global__ void k_nu1f() {
    __shared__ float snu[NC][64];
    __shared__ float sp1[NC][4], sp2[NC][4];
    int b = blockIdx.y;
    int iblk = blockIdx.x;
    int i = iblk * 128 + threadIdx.x;
    int lane = threadIdx.x & 31, wrp = threadIdx.x >> 5;
    float acc[NC];
    #pragma unroll
    for (int j = 0; j < NC; j++) acc[j] = 0.f;
    for (int t0 = 0; t0 < H2; t0 += 64) {
        __syncthreads();
        for (int idx = threadIdx.x; idx < NC * 64; idx += 128)
            snu[idx >> 6][idx & 63] =
                g_nu2[(size_t)(b * NC + (idx >> 6)) * H2 + t0 + (idx & 63)];
        __syncthreads();
        for (int t = 0; t < 64; t++) {
            float w = __bfloat162float(g_Ab[((size_t)b * H2 + t0 + t) * H1 + i]);
            #pragma unroll
            for (int j = 0; j < NC; j++) acc[j] = fmaf(snu[j][t], w, acc[j]);
        }
    }
    float nom = g_nom1[b * H1 + i];
    float lm  = g_l1m[b * H1 + i];
    #pragma unroll
    for (int j = 0; j < NC; j++) {
        float v = acc[j];
        g_nu1fb[(size_t)(b * NC + j) * H1 + i] = __float2bfloat16(v);
        float p1 = v * nom;
        float p2 = fmaxf(-v, 0.f) * lm;
        p1 = warp_sum(p1); p2 = warp_sum(p2);
        if (lane == 0) { sp1[j][wrp] = p1; sp2[j][wrp] = p2; }
    }
    __syncthreads();
    if (threadIdx.x < NC) {
        int j = threadIdx.x;
        int r = b * NC + j;
        g_afp[iblk][r] = sp1[j][0] + sp1[j][1] + sp1[j][2] + sp1[j][3];
        g_crp[iblk][r] = sp2[j][0] + sp2[j][1] + sp2[j][2] + sp2[j][3];
    }
}

// ---------------- K7: output ---------------------------------------------------
__global__ void k_out(float* __restrict__ out) {
    int r = threadIdx.x;
    if (r < NROWS) {
        float Ef = 0.f, af = 0.f, cr = 0.f;
        #pragma unroll
        for (int c = 0; c < NT_TILES; c++) Ef += g_Efp[c][r];
        #pragma unroll
        for (int c = 0; c < NIBLK; c++) { af += g_afp[c][r]; cr += g_crp[c][r]; }
        out[r] = -(af + g_term[r] - EPSV * Ef + cr);
    }
}

// ---------------- launch --------------------------------------------------------
extern "C" void kernel_launch(void* const* d_in, const int* in_sizes, int n_in,
                              void* d_out, int out_size) {
    const float* x  = (const float*)d_in[0];
    const int*   y  = (const int*)  d_in[1];
    const float* W1 = (const float*)d_in[2];
    const float* b1 = (const float*)d_in[3];
    const float* W2 = (const float*)d_in[4];
    const float* b2 = (const float*)d_in[5];
    const float* W3 = (const float*)d_in[6];
    const float* b3 = (const float*)d_in[7];
    float* out = (float*)d_out;

    float* pE2;  cudaGetSymbolAddress((void**)&pE2, g_E2);
    float* pEfp; cudaGetSymbolAddress((void**)&pEfp, g_Efp);
    __nv_bfloat16* pAb;    cudaGetSymbolAddress((void**)&pAb, g_Ab);
    __nv_bfloat16* pnu1fb; cudaGetSymbolAddress((void**)&pnu1fb, g_nu1fb);

    const int SMEM = 4 * STAGEB * 2 + 128 * 2 * 4 + 256;   // 83200
    cudaFuncSetAttribute(k_absgemm_mma, cudaFuncAttributeMaxDynamicSharedMemorySize, SMEM);

    k_r1<<<H1 / 8, 256>>>(W1);
    k_w1t<<<dim3(25, 32), dim3(32, 8)>>>(W1);
    k_zero<<<480, 256>>>();
    k_layer1<<<BATCH * H1 / 8, 256>>>(x, W1, b1);
    k_scaleA<<<16384, 256>>>(W2);
    k_absgemm_mma<<<dim3(8, 1, BATCH), 128, SMEM>>>(pAb, pE2, H2, NT_TILES, 0);
    k_layer2<<<BATCH * H2 / 8, 256>>>(b2);
    k_nu2<<<NROWS, 256>>>(W3, b2, b3, y);
    k_nu1f<<<dim3(NIBLK, BATCH), 128>>>();
    k_absgemm_mma<<<dim3(3, NT_TILES, 1), 128, SMEM>>>(pnu1fb, pEfp, NROWS, 1, NROWS);
    k_out<<<1, 512>>>(out);
}

// round 11
// speedup vs baseline: 1.0828x; 1.0828x over previous
#include <cuda_runtime.h>
#include <cuda_bf16.h>
#include <cstdint>

#define BATCH 32
#define IN_F  784
#define H1    1024
#define H2    1024
#define NC    10
#define EPSV  0.1f
#define NROWS (BATCH * NC)   // 320
#define MROWS1 384           // padded rows for final GEMM (3 x 128)
#define NT_TILES 7           // 7*128 = 896 >= 784
#define SAS2 72              // halves per smem row for BK=64 (144B, conflict-free)
#define STAGEB2 (128 * SAS2 * 2)      // 18432 bytes per stage per matrix
#define NIBLK 8              // i-blocks in k_nu1f

// ---------------- scratch (device globals) ----------------------------------
__device__ float g_r1[H1];
__device__ float g_nom1[BATCH * H1];
__device__ float g_d1[BATCH * H1];
__device__ float g_l1m[BATCH * H1];
__device__ float g_E2[BATCH * H2];
__device__ float g_d2[BATCH * H2];
__device__ float g_l2m[BATCH * H2];
__device__ float g_nu2[NROWS * H2];
__device__ float g_term[NROWS];
__device__ __nv_bfloat16 g_nu1fb[MROWS1 * H1];    // rows 320..383 zero
__device__ __nv_bfloat16 g_W1T[H1 * H1];          // W1^T bf16; rows >=784 zero
__device__ __nv_bfloat16 g_Ab[(size_t)BATCH * H2 * H1];  // W2 * d1[b] (64MB)
__device__ float g_Efp[NT_TILES][NROWS];
__device__ float g_afp[NIBLK][NROWS];
__device__ float g_crp[NIBLK][NROWS];

// ---------------- helpers ----------------------------------------------------
__device__ __forceinline__ uint32_t smem_u32(const void* p) {
    uint32_t a;
    asm("{ .reg .u64 t; cvta.to.shared.u64 t, %1; cvt.u32.u64 %0, t; }" : "=r"(a) : "l"(p));
    return a;
}
__device__ __forceinline__ void cp_async16(uint32_t saddr, const void* gaddr) {
    asm volatile("cp.async.cg.shared.global [%0], [%1], 16;" :: "r"(saddr), "l"(gaddr));
}
__device__ __forceinline__ void cp_commit() {
    asm volatile("cp.async.commit_group;" ::: "memory");
}
template <int N>
__device__ __forceinline__ void cp_wait() {
    asm volatile("cp.async.wait_group %0;" :: "n"(N) : "memory");
}
__device__ __forceinline__ void ldsm_x4(uint32_t& r0, uint32_t& r1, uint32_t& r2,
                                        uint32_t& r3, uint32_t addr) {
    asm volatile("ldmatrix.sync.aligned.m8n8.x4.shared.b16 {%0,%1,%2,%3}, [%4];"
                 : "=r"(r0), "=r"(r1), "=r"(r2), "=r"(r3) : "r"(addr));
}
__device__ __forceinline__ void mma16816(float* c, const uint32_t* a, uint32_t b0,
                                         uint32_t b1) {
    asm volatile(
        "mma.sync.aligned.m16n8k16.row.col.f32.bf16.bf16.f32 "
        "{%0,%1,%2,%3}, {%4,%5,%6,%7}, {%8,%9}, {%0,%1,%2,%3};"
        : "+f"(c[0]), "+f"(c[1]), "+f"(c[2]), "+f"(c[3])
        : "r"(a[0]), "r"(a[1]), "r"(a[2]), "r"(a[3]), "r"(b0), "r"(b1));
}
__device__ __forceinline__ float warp_sum(float v) {
    #pragma unroll
    for (int o = 16; o > 0; o >>= 1) v += __shfl_xor_sync(0xFFFFFFFFu, v, o);
    return v;
}
__device__ __forceinline__ void relu_coeffs(float zl, float zu, float& d, float& lm) {
    if (zl >= 0.f)      { d = 1.f; lm = 0.f; }
    else if (zu <= 0.f) { d = 0.f; lm = 0.f; }
    else                { d = zu / (zu - zl); lm = zl; }
}

// ---------------- K0: r1 ------------------------------------------------------
__global__ void k_r1(const float* __restrict__ W1) {
    int gw = (blockIdx.x * blockDim.x + threadIdx.x) >> 5, lane = threadIdx.x & 31;
    if (gw >= H1) return;
    const float* row = W1 + gw * IN_F;
    float s = 0.f;
    for (int k = lane; k < IN_F; k += 32) s += fabsf(row[k]);
    s = warp_sum(s);
    if (lane == 0) g_r1[gw] = EPSV * s;
}

// ---------------- W1 transpose -> bf16 ---------------------------------------
__global__ void k_w1t(const float* __restrict__ W1) {
    __shared__ float tile[32][33];
    int n0 = blockIdx.x * 32, i0 = blockIdx.y * 32;
    int tx = threadIdx.x, ty = threadIdx.y;      // 32 x 8
    #pragma unroll
    for (int r = 0; r < 4; r++) {
        int i = i0 + ty + 8 * r, n = n0 + tx;
        tile[ty + 8 * r][tx] = (n < IN_F) ? W1[i * IN_F + n] : 0.f;
    }
    __syncthreads();
    #pragma unroll
    for (int r = 0; r < 4; r++) {
        int n = n0 + ty + 8 * r;
        if (n < IN_F)
            g_W1T[(size_t)n * H1 + i0 + tx] = __float2bfloat16(tile[tx][ty + 8 * r]);
    }
}

// ---------------- zero pads ---------------------------------------------------
__global__ void k_zero() {
    int idx = blockIdx.x * 256 + threadIdx.x;       // 480*256 = 122880
    uint32_t* w = (uint32_t*)g_W1T;
    w[IN_F * (H1 / 2) + idx] = 0u;                  // W1T rows 784..1023
    if (idx < (MROWS1 - NROWS) * (H1 / 2)) {        // 32768
        uint32_t* nb = (uint32_t*)g_nu1fb;
        nb[NROWS * (H1 / 2) + idx] = 0u;            // nu1fb rows 320..383
    }
}

// ---------------- K1: layer-1 bounds ------------------------------------------
__global__ void k_layer1(const float* __restrict__ x, const float* __restrict__ W1,
                         const float* __restrict__ b1) {
    int gw = (blockIdx.x * blockDim.x + threadIdx.x) >> 5, lane = threadIdx.x & 31;
    int b = gw >> 10, j = gw & (H1 - 1);
    const float* xr = x + b * IN_F;
    const float* wr = W1 + j * IN_F;
    float s = 0.f;
    for (int k = lane; k < IN_F; k += 32) s += xr[k] * wr[k];
    s = warp_sum(s);
    if (lane == 0) {
        float nom = s + b1[j], r = g_r1[j], d, lm;
        relu_coeffs(nom - r, nom + r, d, lm);
        g_nom1[gw] = nom; g_d1[gw] = d; g_l1m[gw] = lm;
    }
}

// ---------------- A precompute: g_Ab = bf16(W2 * d1[b]) -----------------------
__global__ void k_scaleA(const float* __restrict__ W2) {
    size_t idx = ((size_t)blockIdx.x * 256 + threadIdx.x) * 8;    // 32M elems
    int b = (int)(idx >> 20);
    int i = (int)(idx & 1023);
    size_t wo = idx & 0xFFFFFu;
    float4 w0 = *(const float4*)(W2 + wo);
    float4 w1 = *(const float4*)(W2 + wo + 4);
    const float* dp = g_d1 + b * H1 + i;
    float4 e0 = *(const float4*)dp;
    float4 e1 = *(const float4*)(dp + 4);
    __nv_bfloat162 p0 = __floats2bfloat162_rn(w0.x * e0.x, w0.y * e0.y);
    __nv_bfloat162 p1 = __floats2bfloat162_rn(w0.z * e0.z, w0.w * e0.w);
    __nv_bfloat162 p2 = __floats2bfloat162_rn(w1.x * e1.x, w1.y * e1.y);
    __nv_bfloat162 p3 = __floats2bfloat162_rn(w1.z * e1.z, w1.w * e1.w);
    uint4 o;
    o.x = *(uint32_t*)&p0; o.y = *(uint32_t*)&p1;
    o.z = *(uint32_t*)&p2; o.w = *(uint32_t*)&p3;
    *(uint4*)(g_Ab + idx) = o;
}

// ---------------- tensor-core abs-row-sum GEMM --------------------------------
// Round-8 geometry (256 thr, 2x4 warps, warp tile m64n32, BM=BN=128),
// but BK=64 per stage, 3 stages -> half the barriers.
// RAW rowsum: Eout[b*H2 + blockIdx.y*chunkStride + row] = sum_n |sum_i A[row,i]*B[n,i]|
__global__ void __launch_bounds__(256) k_absgemm_mma(const __nv_bfloat16* __restrict__ Abase,
                                                     float* __restrict__ Eout,
                                                     int rowlimit, int ntPerCta,
                                                     int chunkStride) {
    extern __shared__ char dsm[];
    __nv_bfloat16* sAp = (__nv_bfloat16*)dsm;
    __nv_bfloat16* sBp = sAp + 3 * 128 * SAS2;
    float* sred = (float*)dsm;                       // aliased; used after loop

    const int tid = threadIdx.x, lane = tid & 31, wid = tid >> 5;
    const int warp_m = wid & 1, warp_n = wid >> 1;   // 2 x 4
    const int mtile = blockIdx.x, b = blockIdx.z;
    const int ntBase = blockIdx.y * ntPerCta;
    const __nv_bfloat16* A = Abase + ((size_t)b * H2 + mtile * 128) * H1;
    const __nv_bfloat16* B = g_W1T;

    const int lrow = tid >> 1, lq = (tid & 1) * 4;   // loader: row 0..127, q base

    const int aRow  = warp_m * 64 + (lane & 7) + ((lane >> 3) & 1) * 8;
    const int aColH = (lane >> 4) * 8;
    const int bRow  = warp_n * 32 + (lane & 7) + (lane >> 4) * 8;
    const int bColH = ((lane >> 3) & 1) * 8;

    const uint32_t sA0 = smem_u32(sAp);
    const uint32_t sB0 = smem_u32(sBp);

    auto copy_stage = [&](int g, int buf) {
        int kt = g & 15, nt = ntBase + (g >> 4);
        int k0 = kt * 64;
        uint32_t Ao = sA0 + (uint32_t)buf * STAGEB2;
        uint32_t Bo = sB0 + (uint32_t)buf * STAGEB2;
        #pragma unroll
        for (int s = 0; s < 4; s++) {
            int q = lq + s;
            uint32_t so = (lrow * SAS2 + q * 8) * 2;
            cp_async16(Ao + so, A + (size_t)lrow * H1 + k0 + q * 8);
            cp_async16(Bo + so, B + (size_t)(nt * 128 + lrow) * H1 + k0 + q * 8);
        }
    };

    const int total = ntPerCta * 16;
    copy_stage(0, 0); cp_commit();
    copy_stage(1, 1); cp_commit();

    float rs[4][2];
    #pragma unroll
    for (int mi = 0; mi < 4; mi++) { rs[mi][0] = 0.f; rs[mi][1] = 0.f; }
    float acc[4][4][4];
    #pragma unroll
    for (int mi = 0; mi < 4; mi++)
        #pragma unroll
        for (int ni = 0; ni < 4; ni++)
            #pragma unroll
            for (int e = 0; e < 4; e++) acc[mi][ni][e] = 0.f;

    int buf = 0;
    for (int g = 0; g < total; g++) {
        cp_wait<1>();
        __syncthreads();
        if (g + 2 < total) {
            int nb = buf + 2; if (nb >= 3) nb -= 3;
            copy_stage(g + 2, nb);
        }
        cp_commit();

        uint32_t aBase = sA0 + buf * STAGEB2;
        uint32_t bBase = sB0 + buf * STAGEB2;
        #pragma unroll
        for (int ks = 0; ks < 4; ks++) {
            uint32_t af[4][4];
            #pragma unroll
            for (int mi = 0; mi < 4; mi++)
                ldsm_x4(af[mi][0], af[mi][1], af[mi][2], af[mi][3],
                        aBase + ((aRow + mi * 16) * SAS2 + ks * 16 + aColH) * 2);
            uint32_t bf[2][4];
            #pragma unroll
            for (int np = 0; np < 2; np++)
                ldsm_x4(bf[np][0], bf[np][1], bf[np][2], bf[np][3],
                        bBase + ((bRow + np * 16) * SAS2 + ks * 16 + bColH) * 2);
            #pragma unroll
            for (int mi = 0; mi < 4; mi++)
                #pragma unroll
                for (int ni = 0; ni < 4; ni++)
                    mma16816(acc[mi][ni], af[mi],
                             bf[ni >> 1][(ni & 1) * 2], bf[ni >> 1][(ni & 1) * 2 + 1]);
        }

        if ((g & 15) == 15) {
            #pragma unroll
            for (int mi = 0; mi < 4; mi++)
                #pragma unroll
                for (int ni = 0; ni < 4; ni++) {
                    rs[mi][0] += fabsf(acc[mi][ni][0]) + fabsf(acc[mi][ni][1]);
                    rs[mi][1] += fabsf(acc[mi][ni][2]) + fabsf(acc[mi][ni][3]);
                    acc[mi][ni][0] = 0.f; acc[mi][ni][1] = 0.f;
                    acc[mi][ni][2] = 0.f; acc[mi][ni][3] = 0.f;
                }
        }
        buf++; if (buf == 3) buf = 0;
    }

    __syncthreads();   // all warps done with smem stages before sred aliases them
    #pragma unroll
    for (int mi = 0; mi < 4; mi++)
        #pragma unroll
        for (int h = 0; h < 2; h++) {
            float v = rs[mi][h];
            v += __shfl_xor_sync(0xFFFFFFFFu, v, 1);
            v += __shfl_xor_sync(0xFFFFFFFFu, v, 2);
            if ((lane & 3) == 0)
                sred[(warp_m * 64 + mi * 16 + (lane >> 2) + h * 8) * 4 + warp_n] = v;
        }
    __syncthreads();
    if (tid < 128) {
        float s = sred[tid * 4 + 0] + sred[tid * 4 + 1] + sred[tid * 4 + 2] + sred[tid * 4 + 3];
        int grow = mtile * 128 + tid;
        if (grow < rowlimit)
            Eout[(size_t)b * H2 + (size_t)blockIdx.y * chunkStride + grow] = s;
    }
}

// ---------------- K3: layer-2 bounds (reads bf16 g_Ab) -------------------------
__global__ void k_layer2(const float* __restrict__ b2) {
    int gw = (blockIdx.x * blockDim.x + threadIdx.x) >> 5, lane = threadIdx.x & 31;
    int b = gw >> 10, j = gw & (H2 - 1);
    const __nv_bfloat162* ab = (const __nv_bfloat162*)(g_Ab + ((size_t)b * H2 + j) * H1);
    const float2* nom2 = (const float2*)(g_nom1 + b * H1);
    const float2* lm2  = (const float2*)(g_l1m + b * H1);
    float s1 = 0.f, s2 = 0.f, s3 = 0.f;
    for (int i = lane; i < H1 / 2; i += 32) {
        float2 nu = __bfloat1622float2(ab[i]);
        float2 nm = nom2[i];
        float2 lm = lm2[i];
        s1 += nu.x * nm.x + nu.y * nm.y;
        s2 += fmaxf(-nu.x, 0.f) * lm.x + fmaxf(-nu.y, 0.f) * lm.y;
        s3 += fmaxf(nu.x, 0.f) * lm.x + fmaxf(nu.y, 0.f) * lm.y;
    }
    s1 = warp_sum(s1); s2 = warp_sum(s2); s3 = warp_sum(s3);
    if (lane == 0) {
        float A = s1 + b2[j];
        float E = EPSV * g_E2[gw];
        float d, lm;
        relu_coeffs(A - E + s2, A + E - s3, d, lm);
        g_d2[gw] = d; g_l2m[gw] = lm;
    }
}

// ---------------- K4: nu2 + bias/cross ----------------------------------------
__global__ void k_nu2(const float* __restrict__ W3, const float* __restrict__ b2,
                      const float* __restrict__ b3, const int* __restrict__ y) {
    __shared__ float sAq[256], sBq[256];
    int r = blockIdx.x, b = r / NC, j = r % NC;
    int yb = y[b];
    const float* wy = W3 + (size_t)yb * H2;
    const float* wj = W3 + (size_t)j * H2;
    const float* d2r = g_d2 + b * H2;
    const float* lmr = g_l2m + b * H2;
    float sa = 0.f, sbv = 0.f;
    for (int t = threadIdx.x; t < H2; t += 256) {
        float nu = (wy[t] - wj[t]) * d2r[t];
        g_nu2[(size_t)r * H2 + t] = nu;
        sa += fmaxf(-nu, 0.f) * lmr[t];
        sbv += nu * b2[t];
    }
    sAq[threadIdx.x] = sa; sBq[threadIdx.x] = sbv;
    __syncthreads();
    for (int o = 128; o > 0; o >>= 1) {
        if (threadIdx.x < o) {
            sAq[threadIdx.x] += sAq[threadIdx.x + o];
            sBq[threadIdx.x] += sBq[threadIdx.x + o];
        }
        __syncthreads();
    }
    if (threadIdx.x == 0) g_term[r] = (b3[yb] - b3[j]) + sBq[0] + sAq[0];
}

// ---------------- K5: nu1f = nu2 @ g_Ab[b]; fused final dots -------------------
__global__ void k_nu1f() {
    __shared__ float snu[NC][64];
    __shared__ float sp1[NC][4], sp2[NC][4];
    int b = blockIdx.y;
    int iblk = blockIdx.x;
    int i = iblk * 128 + threadIdx.x;
    int lane = threadIdx.x & 31, wrp = threadIdx.x >> 5;
    float acc[NC];
    #pragma unroll
    for (int j = 0; j < NC; j++) acc[j] = 0.f;
    for (int t0 = 0; t0 < H2; t0 += 64) {
        __syncthreads();
        for (int idx = threadIdx.x; idx < NC * 64; idx += 128)
            snu[idx >> 6][idx & 63] =
                g_nu2[(size_t)(b * NC + (idx >> 6)) * H2 + t0 + (idx & 63)];
        __syncthreads();
        for (int t = 0; t < 64; t++) {
            float w = __bfloat162float(g_Ab[((size_t)b * H2 + t0 + t) * H1 + i]);
            #pragma unroll
            for (int j = 0; j < NC; j++) acc[j] = fmaf(snu[j][t], w, acc[j]);
        }
    }
    float nom = g_nom1[b * H1 + i];
    float lm  = g_l1m[b * H1 + i];
    #pragma unroll
    for (int j = 0; j < NC; j++) {
        float v = acc[j];
        g_nu1fb[(size_t)(b * NC + j) * H1 + i] = __float2bfloat16(v);
        float p1 = v * nom;
        float p2 = fmaxf(-v, 0.f) * lm;
        p1 = warp_sum(p1); p2 = warp_sum(p2);
        if (lane == 0) { sp1[j][wrp] = p1; sp2[j][wrp] = p2; }
    }
    __syncthreads();
    if (threadIdx.x < NC) {
        int j = threadIdx.x;
        int r = b * NC + j;
        g_afp[iblk][r] = sp1[j][0] + sp1[j][1] + sp1[j][2] + sp1[j][3];
        g_crp[iblk][r] = sp2[j][0] + sp2[j][1] + sp2[j][2] + sp2[j][3];
    }
}

// ---------------- K7: output ---------------------------------------------------
__global__ void k_out(float* __restrict__ out) {
    int r = threadIdx.x;
    if (r < NROWS) {
        float Ef = 0.f, af = 0.f, cr = 0.f;
        #pragma unroll
        for (int c = 0; c < NT_TILES; c++) Ef += g_Efp[c][r];
        #pragma unroll
        for (int c = 0; c < NIBLK; c++) { af += g_afp[c][r]; cr += g_crp[c][r]; }
        out[r] = -(af + g_term[r] - EPSV * Ef + cr);
    }
}

// ---------------- launch --------------------------------------------------------
extern "C" void kernel_launch(void* const* d_in, const int* in_sizes, int n_in,
                              void* d_out, int out_size) {
    const float* x  = (const float*)d_in[0];
    const int*   y  = (const int*)  d_in[1];
    const float* W1 = (const float*)d_in[2];
    const float* b1 = (const float*)d_in[3];
    const float* W2 = (const float*)d_in[4];
    const float* b2 = (const float*)d_in[5];
    const float* W3 = (const float*)d_in[6];
    const float* b3 = (const float*)d_in[7];
    float* out = (float*)d_out;

    float* pE2;  cudaGetSymbolAddress((void**)&pE2, g_E2);
    float* pEfp; cudaGetSymbolAddress((void**)&pEfp, g_Efp);
    __nv_bfloat16* pAb;    cudaGetSymbolAddress((void**)&pAb, g_Ab);
    __nv_bfloat16* pnu1fb; cudaGetSymbolAddress((void**)&pnu1fb, g_nu1fb);

    const int SMEM = 3 * STAGEB2 * 2;   // 110592 (sred aliased into stage 0)
    cudaFuncSetAttribute(k_absgemm_mma, cudaFuncAttributeMaxDynamicSharedMemorySize, SMEM);

    k_r1<<<H1 / 8, 256>>>(W1);
    k_w1t<<<dim3(25, 32), dim3(32, 8)>>>(W1);
    k_zero<<<480, 256>>>();
    k_layer1<<<BATCH * H1 / 8, 256>>>(x, W1, b1);
    k_scaleA<<<16384, 256>>>(W2);
    k_absgemm_mma<<<dim3(8, 1, BATCH), 256, SMEM>>>(pAb, pE2, H2, NT_TILES, 0);
    k_layer2<<<BATCH * H2 / 8, 256>>>(b2);
    k_nu2<<<NROWS, 256>>>(W3, b2, b3, y);
    k_nu1f<<<dim3(NIBLK, BATCH), 128>>>();
    k_absgemm_mma<<<dim3(3, NT_TILES, 1), 256, SMEM>>>(pnu1fb, pEfp, NROWS, 1, NROWS);
    k_out<<<1, 512>>>(out);
}

// round 12
// speedup vs baseline: 1.1905x; 1.0994x over previous
#include <cuda_runtime.h>
#include <cuda_bf16.h>
#include <cstdint>

#define BATCH 32
#define IN_F  784
#define H1    1024
#define H2    1024
#define NC    10
#define EPSV  0.1f
#define NROWS (BATCH * NC)   // 320
#define MROWS1 512           // padded rows for final GEMM (2 x 256)
#define NT_TILES 7           // 7*128 = 896 >= 784
#define SASTRIDE 40          // halves per smem row (80B; conflict-free ldmatrix)
#define ASTG (256 * SASTRIDE * 2)   // 20480 B per A stage
#define BSTG (128 * SASTRIDE * 2)   // 10240 B per B stage
#define NIBLK 8              // i-blocks in k_nu1f

// ---------------- scratch (device globals) ----------------------------------
__device__ float g_r1[H1];
__device__ float g_nom1[BATCH * H1];
__device__ float g_d1[BATCH * H1];
__device__ float g_l1m[BATCH * H1];
__device__ float g_E2[BATCH * H2];
__device__ float g_d2[BATCH * H2];
__device__ float g_l2m[BATCH * H2];
__device__ float g_nu2[NROWS * H2];
__device__ float g_term[NROWS];
__device__ __nv_bfloat16 g_nu1fb[MROWS1 * H1];    // rows 320..511 zero
__device__ __nv_bfloat16 g_W1T[H1 * H1];          // W1^T bf16; rows >=784 zero
__device__ __nv_bfloat16 g_Ab[(size_t)BATCH * H2 * H1];  // W2 * d1[b] (64MB)
__device__ float g_Efp[NT_TILES][NROWS];
__device__ float g_afp[NIBLK][NROWS];
__device__ float g_crp[NIBLK][NROWS];

// ---------------- helpers ----------------------------------------------------
__device__ __forceinline__ uint32_t smem_u32(const void* p) {
    uint32_t a;
    asm("{ .reg .u64 t; cvta.to.shared.u64 t, %1; cvt.u32.u64 %0, t; }" : "=r"(a) : "l"(p));
    return a;
}
__device__ __forceinline__ void cp_async16(uint32_t saddr, const void* gaddr) {
    asm volatile("cp.async.cg.shared.global [%0], [%1], 16;" :: "r"(saddr), "l"(gaddr));
}
__device__ __forceinline__ void cp_commit() {
    asm volatile("cp.async.commit_group;" ::: "memory");
}
template <int N>
__device__ __forceinline__ void cp_wait() {
    asm volatile("cp.async.wait_group %0;" :: "n"(N) : "memory");
}
__device__ __forceinline__ void ldsm_x4(uint32_t& r0, uint32_t& r1, uint32_t& r2,
                                        uint32_t& r3, uint32_t addr) {
    asm volatile("ldmatrix.sync.aligned.m8n8.x4.shared.b16 {%0,%1,%2,%3}, [%4];"
                 : "=r"(r0), "=r"(r1), "=r"(r2), "=r"(r3) : "r"(addr));
}
__device__ __forceinline__ void mma16816(float* c, const uint32_t* a, uint32_t b0,
                                         uint32_t b1) {
    asm volatile(
        "mma.sync.aligned.m16n8k16.row.col.f32.bf16.bf16.f32 "
        "{%0,%1,%2,%3}, {%4,%5,%6,%7}, {%8,%9}, {%0,%1,%2,%3};"
        : "+f"(c[0]), "+f"(c[1]), "+f"(c[2]), "+f"(c[3])
        : "r"(a[0]), "r"(a[1]), "r"(a[2]), "r"(a[3]), "r"(b0), "r"(b1));
}
__device__ __forceinline__ float warp_sum(float v) {
    #pragma unroll
    for (int o = 16; o > 0; o >>= 1) v += __shfl_xor_sync(0xFFFFFFFFu, v, o);
    return v;
}
__device__ __forceinline__ void relu_coeffs(float zl, float zu, float& d, float& lm) {
    if (zl >= 0.f)      { d = 1.f; lm = 0.f; }
    else if (zu <= 0.f) { d = 0.f; lm = 0.f; }
    else                { d = zu / (zu - zl); lm = zl; }
}

// ---------------- K_prep: fused r1 + W1 transpose + zero pads -----------------
// blocks 0..799: w1t tiles; 800..927: r1; 928..1407: zero pads. 256 thr each.
__global__ void k_prep(const float* __restrict__ W1) {
    int bx = blockIdx.x;
    if (bx < 800) {
        __shared__ float tile[32][33];
        int n0 = (bx % 25) * 32, i0 = (bx / 25) * 32;
        int tx = threadIdx.x & 31, ty = threadIdx.x >> 5;   // 32 x 8
        #pragma unroll
        for (int r = 0; r < 4; r++) {
            int i = i0 + ty + 8 * r, n = n0 + tx;
            tile[ty + 8 * r][tx] = (n < IN_F) ? W1[i * IN_F + n] : 0.f;
        }
        __syncthreads();
        #pragma unroll
        for (int r = 0; r < 4; r++) {
            int n = n0 + ty + 8 * r;
            if (n < IN_F)
                g_W1T[(size_t)n * H1 + i0 + tx] = __float2bfloat16(tile[tx][ty + 8 * r]);
        }
    } else if (bx < 928) {
        int gw = ((bx - 800) * 256 + threadIdx.x) >> 5, lane = threadIdx.x & 31;
        const float* row = W1 + gw * IN_F;
        float s = 0.f;
        for (int k = lane; k < IN_F; k += 32) s += fabsf(row[k]);
        s = warp_sum(s);
        if (lane == 0) g_r1[gw] = EPSV * s;
    } else {
        int idx = (bx - 928) * 256 + threadIdx.x;       // 480*256 = 122880
        uint32_t* w = (uint32_t*)g_W1T;
        w[IN_F * (H1 / 2) + idx] = 0u;                  // W1T rows 784..1023
        if (idx < (MROWS1 - NROWS) * (H1 / 2)) {        // 98304
            uint32_t* nb = (uint32_t*)g_nu1fb;
            nb[NROWS * (H1 / 2) + idx] = 0u;            // nu1fb rows 320..511
        }
    }
}

// ---------------- K1: layer-1 bounds ------------------------------------------
__global__ void k_layer1(const float* __restrict__ x, const float* __restrict__ W1,
                         const float* __restrict__ b1) {
    int gw = (blockIdx.x * blockDim.x + threadIdx.x) >> 5, lane = threadIdx.x & 31;
    int b = gw >> 10, j = gw & (H1 - 1);
    const float* xr = x + b * IN_F;
    const float* wr = W1 + j * IN_F;
    float s = 0.f;
    for (int k = lane; k < IN_F; k += 32) s += xr[k] * wr[k];
    s = warp_sum(s);
    if (lane == 0) {
        float nom = s + b1[j], r = g_r1[j], d, lm;
        relu_coeffs(nom - r, nom + r, d, lm);
        g_nom1[gw] = nom; g_d1[gw] = d; g_l1m[gw] = lm;
    }
}

// ---------------- A precompute: g_Ab = bf16(W2 * d1[b]) -----------------------
__global__ void k_scaleA(const float* __restrict__ W2) {
    size_t idx = ((size_t)blockIdx.x * 256 + threadIdx.x) * 8;    // 32M elems
    int b = (int)(idx >> 20);
    int i = (int)(idx & 1023);
    size_t wo = idx & 0xFFFFFu;
    float4 w0 = *(const float4*)(W2 + wo);
    float4 w1 = *(const float4*)(W2 + wo + 4);
    const float* dp = g_d1 + b * H1 + i;
    float4 e0 = *(const float4*)dp;
    float4 e1 = *(const float4*)(dp + 4);
    __nv_bfloat162 p0 = __floats2bfloat162_rn(w0.x * e0.x, w0.y * e0.y);
    __nv_bfloat162 p1 = __floats2bfloat162_rn(w0.z * e0.z, w0.w * e0.w);
    __nv_bfloat162 p2 = __floats2bfloat162_rn(w1.x * e1.x, w1.y * e1.y);
    __nv_bfloat162 p3 = __floats2bfloat162_rn(w1.z * e1.z, w1.w * e1.w);
    uint4 o;
    o.x = *(uint32_t*)&p0; o.y = *(uint32_t*)&p1;
    o.z = *(uint32_t*)&p2; o.w = *(uint32_t*)&p3;
    *(uint4*)(g_Ab + idx) = o;
}

// ---------------- tensor-core abs-row-sum GEMM --------------------------------
// BM=256, BN=128, 512 thr (4x4 warps, warp tile m64n32), BK=32, 4 stages.
// RAW rowsum: Eout[b*H2 + blockIdx.y*chunkStride + row] = sum_n |sum_i A[row,i]*B[n,i]|
__global__ void __launch_bounds__(512, 1)
k_absgemm_mma(const __nv_bfloat16* __restrict__ Abase, float* __restrict__ Eout,
              int rowlimit, int ntPerCta, int chunkStride) {
    extern __shared__ char dsm[];
    __nv_bfloat16* sAp = (__nv_bfloat16*)dsm;
    __nv_bfloat16* sBp = sAp + 4 * 256 * SASTRIDE;
    float* sred = (float*)dsm;                       // aliased after main loop

    const int tid = threadIdx.x, lane = tid & 31, wid = tid >> 5;
    const int warp_m = wid & 3, warp_n = wid >> 2;   // 4 x 4
    const int mtile = blockIdx.x, b = blockIdx.z;
    const int ntBase = blockIdx.y * ntPerCta;
    const __nv_bfloat16* A = Abase + ((size_t)b * H2 + mtile * 256) * H1;
    const __nv_bfloat16* B = g_W1T;

    const int aRow  = warp_m * 64 + (lane & 7) + ((lane >> 3) & 1) * 8;
    const int aColH = (lane >> 4) * 8;
    const int bRow  = warp_n * 32 + (lane & 7) + (lane >> 4) * 8;
    const int bColH = ((lane >> 3) & 1) * 8;

    const uint32_t sA0 = smem_u32(sAp);
    const uint32_t sB0 = smem_u32(sBp);

    // loaders: A 256 rows x 4 slots = 1024 ops (2/thread); B 128 x 4 = 512 (1/thread)
    const int alrow = tid >> 1, alq = (tid & 1) * 2;
    const int blrow = tid >> 2, blq = tid & 3;

    auto copy_stage = [&](int g, int buf) {
        int kt = g & 31, nt = ntBase + (g >> 5);
        int k0 = kt * 32;
        uint32_t Ao = sA0 + (uint32_t)buf * ASTG;
        uint32_t Bo = sB0 + (uint32_t)buf * BSTG;
        #pragma unroll
        for (int s = 0; s < 2; s++) {
            int q = alq + s;
            cp_async16(Ao + (alrow * SASTRIDE + q * 8) * 2,
                       A + (size_t)alrow * H1 + k0 + q * 8);
        }
        cp_async16(Bo + (blrow * SASTRIDE + blq * 8) * 2,
                   B + (size_t)(nt * 128 + blrow) * H1 + k0 + blq * 8);
    };

    const int total = ntPerCta * 32;
    copy_stage(0, 0); cp_commit();
    copy_stage(1, 1); cp_commit();
    copy_stage(2, 2); cp_commit();

    float rs[4][2];
    #pragma unroll
    for (int mi = 0; mi < 4; mi++) { rs[mi][0] = 0.f; rs[mi][1] = 0.f; }
    float acc[4][4][4];
    #pragma unroll
    for (int mi = 0; mi < 4; mi++)
        #pragma unroll
        for (int ni = 0; ni < 4; ni++)
            #pragma unroll
            for (int e = 0; e < 4; e++) acc[mi][ni][e] = 0.f;

    for (int g = 0; g < total; g++) {
        cp_wait<2>();
        __syncthreads();
        if (g + 3 < total) copy_stage(g + 3, (g + 3) & 3);
        cp_commit();

        int buf = g & 3;
        uint32_t aBase = sA0 + buf * ASTG;
        uint32_t bBase = sB0 + buf * BSTG;
        #pragma unroll
        for (int ks = 0; ks < 2; ks++) {
            uint32_t af[4][4];
            #pragma unroll
            for (int mi = 0; mi < 4; mi++)
                ldsm_x4(af[mi][0], af[mi][1], af[mi][2], af[mi][3],
                        aBase + ((aRow + mi * 16) * SASTRIDE + ks * 16 + aColH) * 2);
            uint32_t bf[2][4];
            #pragma unroll
            for (int np = 0; np < 2; np++)
                ldsm_x4(bf[np][0], bf[np][1], bf[np][2], bf[np][3],
                        bBase + ((bRow + np * 16) * SASTRIDE + ks * 16 + bColH) * 2);
            #pragma unroll
            for (int mi = 0; mi < 4; mi++)
                #pragma unroll
                for (int ni = 0; ni < 4; ni++)
                    mma16816(acc[mi][ni], af[mi],
                             bf[ni >> 1][(ni & 1) * 2], bf[ni >> 1][(ni & 1) * 2 + 1]);
        }

        if ((g & 31) == 31) {
            #pragma unroll
            for (int mi = 0; mi < 4; mi++)
                #pragma unroll
                for (int ni = 0; ni < 4; ni++) {
                    rs[mi][0] += fabsf(acc[mi][ni][0]) + fabsf(acc[mi][ni][1]);
                    rs[mi][1] += fabsf(acc[mi][ni][2]) + fabsf(acc[mi][ni][3]);
                    acc[mi][ni][0] = 0.f; acc[mi][ni][1] = 0.f;
                    acc[mi][ni][2] = 0.f; acc[mi][ni][3] = 0.f;
                }
        }
    }

    __syncthreads();   // stages dead; sred aliases stage memory
    #pragma unroll
    for (int mi = 0; mi < 4; mi++)
        #pragma unroll
        for (int h = 0; h < 2; h++) {
            float v = rs[mi][h];
            v += __shfl_xor_sync(0xFFFFFFFFu, v, 1);
            v += __shfl_xor_sync(0xFFFFFFFFu, v, 2);
            if ((lane & 3) == 0)
                sred[(warp_m * 64 + mi * 16 + (lane >> 2) + h * 8) * 4 + warp_n] = v;
        }
    __syncthreads();
    if (tid < 256) {
        float s = sred[tid * 4 + 0] + sred[tid * 4 + 1] + sred[tid * 4 + 2] + sred[tid * 4 + 3];
        int grow = mtile * 256 + tid;
        if (grow < rowlimit)
            Eout[(size_t)b * H2 + (size_t)blockIdx.y * chunkStride + grow] = s;
    }
}

// ---------------- K3: layer-2 bounds (reads bf16 g_Ab) -------------------------
__global__ void k_layer2(const float* __restrict__ b2) {
    int gw = (blockIdx.x * blockDim.x + threadIdx.x) >> 5, lane = threadIdx.x & 31;
    int b = gw >> 10, j = gw & (H2 - 1);
    const __nv_bfloat162* ab = (const __nv_bfloat162*)(g_Ab + ((size_t)b * H2 + j) * H1);
    const float2* nom2 = (const float2*)(g_nom1 + b * H1);
    const float2* lm2  = (const float2*)(g_l1m + b * H1);
    float s1 = 0.f, s2 = 0.f, s3 = 0.f;
    for (int i = lane; i < H1 / 2; i += 32) {
        float2 nu = __bfloat1622float2(ab[i]);
        float2 nm = nom2[i];
        float2 lm = lm2[i];
        s1 += nu.x * nm.x + nu.y * nm.y;
        s2 += fmaxf(-nu.x, 0.f) * lm.x + fmaxf(-nu.y, 0.f) * lm.y;
        s3 += fmaxf(nu.x, 0.f) * lm.x + fmaxf(nu.y, 0.f) * lm.y;
    }
    s1 = warp_sum(s1); s2 = warp_sum(s2); s3 = warp_sum(s3);
    if (lane == 0) {
        float A = s1 + b2[j];
        float E = EPSV * g_E2[gw];
        float d, lm;
        relu_coeffs(A - E + s2, A + E - s3, d, lm);
        g_d2[gw] = d; g_l2m[gw] = lm;
    }
}

// ---------------- K4: nu2 + bias/cross ----------------------------------------
__global__ void k_nu2(const float* __restrict__ W3, const float* __restrict__ b2,
                      const float* __restrict__ b3, const int* __restrict__ y) {
    __shared__ float sAq[256], sBq[256];
    int r = blockIdx.x, b = r / NC, j = r % NC;
    int yb = y[b];
    const float* wy = W3 + (size_t)yb * H2;
    const float* wj = W3 + (size_t)j * H2;
    const float* d2r = g_d2 + b * H2;
    const float* lmr = g_l2m + b * H2;
    float sa = 0.f, sbv = 0.f;
    for (int t = threadIdx.x; t < H2; t += 256) {
        float nu = (wy[t] - wj[t]) * d2r[t];
        g_nu2[(size_t)r * H2 + t] = nu;
        sa += fmaxf(-nu, 0.f) * lmr[t];
        sbv += nu * b2[t];
    }
    sAq[threadIdx.x] = sa; sBq[threadIdx.x] = sbv;
    __syncthreads();
    for (int o = 128; o > 0; o >>= 1) {
        if (threadIdx.x < o) {
            sAq[threadIdx.x] += sAq[threadIdx.x + o];
            sBq[threadIdx.x] += sBq[threadIdx.x + o];
        }
        __syncthreads();
    }
    if (threadIdx.x == 0) g_term[r] = (b3[yb] - b3[j]) + sBq[0] + sAq[0];
}

// ---------------- K5: nu1f = nu2 @ g_Ab[b]; fused final dots -------------------
__global__ void k_nu1f() {
    __shared__ float snu[NC][64];
    __shared__ float sp1[NC][4], sp2[NC][4];
    int b = blockIdx.y;
    int iblk = blockIdx.x;
    int i = iblk * 128 + threadIdx.x;
    int lane = threadIdx.x & 31, wrp = threadIdx.x >> 5;
    float acc[NC];
    #pragma unroll
    for (int j = 0; j < NC; j++) acc[j] = 0.f;
    for (int t0 = 0; t0 < H2; t0 += 64) {
        __syncthreads();
        for (int idx = threadIdx.x; idx < NC * 64; idx += 128)
            snu[idx >> 6][idx & 63] =
                g_nu2[(size_t)(b * NC + (idx >> 6)) * H2 + t0 + (idx & 63)];
        __syncthreads();
        for (int t = 0; t < 64; t++) {
            float w = __bfloat162float(g_Ab[((size_t)b * H2 + t0 + t) * H1 + i]);
            #pragma unroll
            for (int j = 0; j < NC; j++) acc[j] = fmaf(snu[j][t], w, acc[j]);
        }
    }
    float nom = g_nom1[b * H1 + i];
    float lm  = g_l1m[b * H1 + i];
    #pragma unroll
    for (int j = 0; j < NC; j++) {
        float v = acc[j];
        g_nu1fb[(size_t)(b * NC + j) * H1 + i] = __float2bfloat16(v);
        float p1 = v * nom;
        float p2 = fmaxf(-v, 0.f) * lm;
        p1 = warp_sum(p1); p2 = warp_sum(p2);
        if (lane == 0) { sp1[j][wrp] = p1; sp2[j][wrp] = p2; }
    }
    __syncthreads();
    if (threadIdx.x < NC) {
        int j = threadIdx.x;
        int r = b * NC + j;
        g_afp[iblk][r] = sp1[j][0] + sp1[j][1] + sp1[j][2] + sp1[j][3];
        g_crp[iblk][r] = sp2[j][0] + sp2[j][1] + sp2[j][2] + sp2[j][3];
    }
}

// ---------------- K7: output ---------------------------------------------------
__global__ void k_out(float* __restrict__ out) {
    int r = threadIdx.x;
    if (r < NROWS) {
        float Ef = 0.f, af = 0.f, cr = 0.f;
        #pragma unroll
        for (int c = 0; c < NT_TILES; c++) Ef += g_Efp[c][r];
        #pragma unroll
        for (int c = 0; c < NIBLK; c++) { af += g_afp[c][r]; cr += g_crp[c][r]; }
        out[r] = -(af + g_term[r] - EPSV * Ef + cr);
    }
}

// ---------------- launch --------------------------------------------------------
extern "C" void kernel_launch(void* const* d_in, const int* in_sizes, int n_in,
                              void* d_out, int out_size) {
    const float* x  = (const float*)d_in[0];
    const int*   y  = (const int*)  d_in[1];
    const float* W1 = (const float*)d_in[2];
    const float* b1 = (const float*)d_in[3];
    const float* W2 = (const float*)d_in[4];
    const float* b2 = (const float*)d_in[5];
    const float* W3 = (const float*)d_in[6];
    const float* b3 = (const float*)d_in[7];
    float* out = (float*)d_out;

    float* pE2;  cudaGetSymbolAddress((void**)&pE2, g_E2);
    float* pEfp; cudaGetSymbolAddress((void**)&pEfp, g_Efp);
    __nv_bfloat16* pAb;    cudaGetSymbolAddress((void**)&pAb, g_Ab);
    __nv_bfloat16* pnu1fb; cudaGetSymbolAddress((void**)&pnu1fb, g_nu1fb);

    const int SMEM = 4 * (ASTG + BSTG);   // 122880 (sred aliased into stage 0)
    cudaFuncSetAttribute(k_absgemm_mma, cudaFuncAttributeMaxDynamicSharedMemorySize, SMEM);

    k_prep<<<1408, 256>>>(W1);
    k_layer1<<<BATCH * H1 / 8, 256>>>(x, W1, b1);
    k_scaleA<<<16384, 256>>>(W2);
    k_absgemm_mma<<<dim3(4, 1, BATCH), 512, SMEM>>>(pAb, pE2, H2, NT_TILES, 0);   // profiled
    k_layer2<<<BATCH * H2 / 8, 256>>>(b2);
    k_nu2<<<NROWS, 256>>>(W3, b2, b3, y);
    k_nu1f<<<dim3(NIBLK, BATCH), 128>>>();
    k_absgemm_mma<<<dim3(2, NT_TILES, 1), 512, SMEM>>>(pnu1fb, pEfp, NROWS, 1, NROWS);
    k_out<<<1, 512>>>(out);
}

// round 15
// speedup vs baseline: 1.1942x; 1.0031x over previous
#include <cuda_runtime.h>
#include <cuda_bf16.h>
#include <cstdint>

#define BATCH 32
#define IN_F  784
#define H1    1024
#define H2    1024
#define NC    10
#define EPSV  0.1f
#define NROWS (BATCH * NC)   // 320
#define MROWS1 512           // padded rows for final GEMM (2 x 256)
#define NT_TILES 7           // 7*128 = 896 >= 784
#define SAS2 72              // halves per smem row for BK=64 (144B)
#define ASTG (256 * SAS2 * 2)   // 36864 B per A stage
#define BSTG (128 * SAS2 * 2)   // 18432 B per B stage
#define NIBLK 8              // i-blocks in k_nu1f

// ---------------- scratch (device globals) ----------------------------------
__device__ float g_r1[H1];
__device__ float g_nom1[BATCH * H1];
__device__ float g_d1[BATCH * H1];
__device__ float g_l1m[BATCH * H1];
__device__ float g_E2[BATCH * H2];
__device__ float g_d2[BATCH * H2];
__device__ float g_l2m[BATCH * H2];
__device__ float g_nu2[NROWS * H2];
__device__ float g_term[NROWS];
__device__ __nv_bfloat16 g_nu1fb[MROWS1 * H1];    // rows 320..511 zero
__device__ __nv_bfloat16 g_W1T[H1 * H1];          // W1^T bf16; rows >=784 zero
__device__ __nv_bfloat16 g_Ab[(size_t)BATCH * H2 * H1];  // W2 * d1[b] (64MB)
__device__ float g_Efp[NT_TILES][NROWS];
__device__ float g_afp[NIBLK][NROWS];
__device__ float g_crp[NIBLK][NROWS];

// ---------------- helpers ----------------------------------------------------
__device__ __forceinline__ uint32_t smem_u32(const void* p) {
    uint32_t a;
    asm("{ .reg .u64 t; cvta.to.shared.u64 t, %1; cvt.u32.u64 %0, t; }" : "=r"(a) : "l"(p));
    return a;
}
__device__ __forceinline__ void cp_async16(uint32_t saddr, const void* gaddr) {
    asm volatile("cp.async.cg.shared.global [%0], [%1], 16;" :: "r"(saddr), "l"(gaddr));
}
__device__ __forceinline__ void cp_commit() {
    asm volatile("cp.async.commit_group;" ::: "memory");
}
template <int N>
__device__ __forceinline__ void cp_wait() {
    asm volatile("cp.async.wait_group %0;" :: "n"(N) : "memory");
}
__device__ __forceinline__ void ldsm_x4(uint32_t& r0, uint32_t& r1, uint32_t& r2,
                                        uint32_t& r3, uint32_t addr) {
    asm volatile("ldmatrix.sync.aligned.m8n8.x4.shared.b16 {%0,%1,%2,%3}, [%4];"
                 : "=r"(r0), "=r"(r1), "=r"(r2), "=r"(r3) : "r"(addr));
}
__device__ __forceinline__ void mma16816(float* c, const uint32_t* a, uint32_t b0,
                                         uint32_t b1) {
    asm volatile(
        "mma.sync.aligned.m16n8k16.row.col.f32.bf16.bf16.f32 "
        "{%0,%1,%2,%3}, {%4,%5,%6,%7}, {%8,%9}, {%0,%1,%2,%3};"
        : "+f"(c[0]), "+f"(c[1]), "+f"(c[2]), "+f"(c[3])
        : "r"(a[0]), "r"(a[1]), "r"(a[2]), "r"(a[3]), "r"(b0), "r"(b1));
}
__device__ __forceinline__ float warp_sum(float v) {
    #pragma unroll
    for (int o = 16; o > 0; o >>= 1) v += __shfl_xor_sync(0xFFFFFFFFu, v, o);
    return v;
}
__device__ __forceinline__ void relu_coeffs(float zl, float zu, float& d, float& lm) {
    if (zl >= 0.f)      { d = 1.f; lm = 0.f; }
    else if (zu <= 0.f) { d = 0.f; lm = 0.f; }
    else                { d = zu / (zu - zl); lm = zl; }
}

// ---------------- K_prep: fused r1 + W1 transpose + zero pads -----------------
__global__ void k_prep(const float* __restrict__ W1) {
    int bx = blockIdx.x;
    if (bx < 800) {
        __shared__ float tile[32][33];
        int n0 = (bx % 25) * 32, i0 = (bx / 25) * 32;
        int tx = threadIdx.x & 31, ty = threadIdx.x >> 5;   // 32 x 8
        #pragma unroll
        for (int r = 0; r < 4; r++) {
            int i = i0 + ty + 8 * r, n = n0 + tx;
            tile[ty + 8 * r][tx] = (n < IN_F) ? W1[i * IN_F + n] : 0.f;
        }
        __syncthreads();
        #pragma unroll
        for (int r = 0; r < 4; r++) {
            int n = n0 + ty + 8 * r;
            if (n < IN_F)
                g_W1T[(size_t)n * H1 + i0 + tx] = __float2bfloat16(tile[tx][ty + 8 * r]);
        }
    } else if (bx < 928) {
        int gw = ((bx - 800) * 256 + threadIdx.x) >> 5, lane = threadIdx.x & 31;
        const float* row = W1 + gw * IN_F;
        float s = 0.f;
        for (int k = lane; k < IN_F; k += 32) s += fabsf(row[k]);
        s = warp_sum(s);
        if (lane == 0) g_r1[gw] = EPSV * s;
    } else {
        int idx = (bx - 928) * 256 + threadIdx.x;       // 480*256 = 122880
        uint32_t* w = (uint32_t*)g_W1T;
        w[IN_F * (H1 / 2) + idx] = 0u;                  // W1T rows 784..1023
        if (idx < (MROWS1 - NROWS) * (H1 / 2)) {        // 98304
            uint32_t* nb = (uint32_t*)g_nu1fb;
            nb[NROWS * (H1 / 2) + idx] = 0u;            // nu1fb rows 320..511
        }
    }
}

// ---------------- K1: layer-1 bounds ------------------------------------------
__global__ void k_layer1(const float* __restrict__ x, const float* __restrict__ W1,
                         const float* __restrict__ b1) {
    int gw = (blockIdx.x * blockDim.x + threadIdx.x) >> 5, lane = threadIdx.x & 31;
    int b = gw >> 10, j = gw & (H1 - 1);
    const float* xr = x + b * IN_F;
    const float* wr = W1 + j * IN_F;
    float s = 0.f;
    for (int k = lane; k < IN_F; k += 32) s += xr[k] * wr[k];
    s = warp_sum(s);
    if (lane == 0) {
        float nom = s + b1[j], r = g_r1[j], d, lm;
        relu_coeffs(nom - r, nom + r, d, lm);
        g_nom1[gw] = nom; g_d1[gw] = d; g_l1m[gw] = lm;
    }
}

// ---------------- A precompute: g_Ab = bf16(W2 * d1[b]) -----------------------
__global__ void k_scaleA(const float* __restrict__ W2) {
    size_t idx = ((size_t)blockIdx.x * 256 + threadIdx.x) * 8;    // 32M elems
    int b = (int)(idx >> 20);
    int i = (int)(idx & 1023);
    size_t wo = idx & 0xFFFFFu;
    float4 w0 = *(const float4*)(W2 + wo);
    float4 w1 = *(const float4*)(W2 + wo + 4);
    const float* dp = g_d1 + b * H1 + i;
    float4 e0 = *(const float4*)dp;
    float4 e1 = *(const float4*)(dp + 4);
    __nv_bfloat162 p0 = __floats2bfloat162_rn(w0.x * e0.x, w0.y * e0.y);
    __nv_bfloat162 p1 = __floats2bfloat162_rn(w0.z * e0.z, w0.w * e0.w);
    __nv_bfloat162 p2 = __floats2bfloat162_rn(w1.x * e1.x, w1.y * e1.y);
    __nv_bfloat162 p3 = __floats2bfloat162_rn(w1.z * e1.z, w1.w * e1.w);
    uint4 o;
    o.x = *(uint32_t*)&p0; o.y = *(uint32_t*)&p1;
    o.z = *(uint32_t*)&p2; o.w = *(uint32_t*)&p3;
    *(uint4*)(g_Ab + idx) = o;
}

// ---------------- tensor-core abs-row-sum GEMM --------------------------------
// BM=256, BN=128, 512 thr (4x4 warps, warp tile m64n32), BK=64, 4 stages (221KB).
// RAW rowsum: Eout[b*H2 + blockIdx.y*chunkStride + row] = sum_n |sum_i A[row,i]*B[n,i]|
__global__ void __launch_bounds__(512, 1)
k_absgemm_mma(const __nv_bfloat16* __restrict__ Abase, float* __restrict__ Eout,
              int rowlimit, int ntPerCta, int chunkStride) {
    extern __shared__ char dsm[];
    __nv_bfloat16* sAp = (__nv_bfloat16*)dsm;
    __nv_bfloat16* sBp = sAp + 4 * 256 * SAS2;
    float* sred = (float*)dsm;                       // aliased after main loop

    const int tid = threadIdx.x, lane = tid & 31, wid = tid >> 5;
    const int warp_m = wid & 3, warp_n = wid >> 2;   // 4 x 4
    const int mtile = blockIdx.x, b = blockIdx.z;
    const int ntBase = blockIdx.y * ntPerCta;
    const __nv_bfloat16* A = Abase + ((size_t)b * H2 + mtile * 256) * H1;
    const __nv_bfloat16* B = g_W1T;

    const int aRow  = warp_m * 64 + (lane & 7) + ((lane >> 3) & 1) * 8;
    const int aColH = (lane >> 4) * 8;
    const int bRow  = warp_n * 32 + (lane & 7) + (lane >> 4) * 8;
    const int bColH = ((lane >> 3) & 1) * 8;

    const uint32_t sA0 = smem_u32(sAp);
    const uint32_t sB0 = smem_u32(sBp);

    // loaders (BK=64): A 256 rows x 8 slots = 2048 ops -> 4/thread;
    //                  B 128 rows x 8 slots = 1024 ops -> 2/thread
    const int alrow = tid >> 1, alq = (tid & 1) * 4;
    const int blrow = tid >> 2, blq = (tid & 3) * 2;

    auto copy_stage = [&](int g, int buf) {
        int kt = g & 15, nt = ntBase + (g >> 4);
        int k0 = kt * 64;
        uint32_t Ao = sA0 + (uint32_t)buf * ASTG;
        uint32_t Bo = sB0 + (uint32_t)buf * BSTG;
        #pragma unroll
        for (int s = 0; s < 4; s++) {
            int q = alq + s;
            cp_async16(Ao + (alrow * SAS2 + q * 8) * 2,
                       A + (size_t)alrow * H1 + k0 + q * 8);
        }
        #pragma unroll
        for (int s = 0; s < 2; s++) {
            int q = blq + s;
            cp_async16(Bo + (blrow * SAS2 + q * 8) * 2,
                       B + (size_t)(nt * 128 + blrow) * H1 + k0 + q * 8);
        }
    };

    const int total = ntPerCta * 16;
    copy_stage(0, 0); cp_commit();
    copy_stage(1, 1); cp_commit();
    copy_stage(2, 2); cp_commit();

    float rs[4][2];
    #pragma unroll
    for (int mi = 0; mi < 4; mi++) { rs[mi][0] = 0.f; rs[mi][1] = 0.f; }
    float acc[4][4][4];
    #pragma unroll
    for (int mi = 0; mi < 4; mi++)
        #pragma unroll
        for (int ni = 0; ni < 4; ni++)
            #pragma unroll
            for (int e = 0; e < 4; e++) acc[mi][ni][e] = 0.f;

    for (int g = 0; g < total; g++) {
        cp_wait<2>();
        __syncthreads();
        if (g + 3 < total) copy_stage(g + 3, (g + 3) & 3);
        cp_commit();

        int buf = g & 3;
        uint32_t aBase = sA0 + buf * ASTG;
        uint32_t bBase = sB0 + buf * BSTG;
        #pragma unroll
        for (int ks = 0; ks < 4; ks++) {
            uint32_t af[4][4];
            #pragma unroll
            for (int mi = 0; mi < 4; mi++)
                ldsm_x4(af[mi][0], af[mi][1], af[mi][2], af[mi][3],
                        aBase + ((aRow + mi * 16) * SAS2 + ks * 16 + aColH) * 2);
            uint32_t bf[2][4];
            #pragma unroll
            for (int np = 0; np < 2; np++)
                ldsm_x4(bf[np][0], bf[np][1], bf[np][2], bf[np][3],
                        bBase + ((bRow + np * 16) * SAS2 + ks * 16 + bColH) * 2);
            #pragma unroll
            for (int mi = 0; mi < 4; mi++)
                #pragma unroll
                for (int ni = 0; ni < 4; ni++)
                    mma16816(acc[mi][ni], af[mi],
                             bf[ni >> 1][(ni & 1) * 2], bf[ni >> 1][(ni & 1) * 2 + 1]);
        }

        if ((g & 15) == 15) {
            #pragma unroll
            for (int mi = 0; mi < 4; mi++)
                #pragma unroll
                for (int ni = 0; ni < 4; ni++) {
                    rs[mi][0] += fabsf(acc[mi][ni][0]) + fabsf(acc[mi][ni][1]);
                    rs[mi][1] += fabsf(acc[mi][ni][2]) + fabsf(acc[mi][ni][3]);
                    acc[mi][ni][0] = 0.f; acc[mi][ni][1] = 0.f;
                    acc[mi][ni][2] = 0.f; acc[mi][ni][3] = 0.f;
                }
        }
    }

    __syncthreads();   // stages dead; sred aliases stage memory
    #pragma unroll
    for (int mi = 0; mi < 4; mi++)
        #pragma unroll
        for (int h = 0; h < 2; h++) {
            float v = rs[mi][h];
            v += __shfl_xor_sync(0xFFFFFFFFu, v, 1);
            v += __shfl_xor_sync(0xFFFFFFFFu, v, 2);
            if ((lane & 3) == 0)
                sred[(warp_m * 64 + mi * 16 + (lane >> 2) + h * 8) * 4 + warp_n] = v;
        }
    __syncthreads();
    if (tid < 256) {
        float s = sred[tid * 4 + 0] + sred[tid * 4 + 1] + sred[tid * 4 + 2] + sred[tid * 4 + 3];
        int grow = mtile * 256 + tid;
        if (grow < rowlimit)
            Eout[(size_t)b * H2 + (size_t)blockIdx.y * chunkStride + grow] = s;
    }
}

// ---------------- K3: layer-2 bounds (reads bf16 g_Ab) -------------------------
__global__ void k_layer2(const float* __restrict__ b2) {
    int gw = (blockIdx.x * blockDim.x + threadIdx.x) >> 5, lane = threadIdx.x & 31;
    int b = gw >> 10, j = gw & (H2 - 1);
    const __nv_bfloat162* ab = (const __nv_bfloat162*)(g_Ab + ((size_t)b * H2 + j) * H1);
    const float2* nom2 = (const float2*)(g_nom1 + b * H1);
    const float2* lm2  = (const float2*)(g_l1m + b * H1);
    float s1 = 0.f, s2 = 0.f, s3 = 0.f;
    for (int i = lane; i < H1 / 2; i += 32) {
        float2 nu = __bfloat1622float2(ab[i]);
        float2 nm = nom2[i];
        float2 lm = lm2[i];
        s1 += nu.x * nm.x + nu.y * nm.y;
        s2 += fmaxf(-nu.x, 0.f) * lm.x + fmaxf(-nu.y, 0.f) * lm.y;
        s3 += fmaxf(nu.x, 0.f) * lm.x + fmaxf(nu.y, 0.f) * lm.y;
    }
    s1 = warp_sum(s1); s2 = warp_sum(s2); s3 = warp_sum(s3);
    if (lane == 0) {
        float A = s1 + b2[j];
        float E = EPSV * g_E2[gw];
        float d, lm;
        relu_coeffs(A - E + s2, A + E - s3, d, lm);
        g_d2[gw] = d; g_l2m[gw] = lm;
    }
}

// ---------------- K4: nu2 + bias/cross ----------------------------------------
__global__ void k_nu2(const float* __restrict__ W3, const float* __restrict__ b2,
                      const float* __restrict__ b3, const int* __restrict__ y) {
    __shared__ float sAq[256], sBq[256];
    int r = blockIdx.x, b = r / NC, j = r % NC;
    int yb = y[b];
    const float* wy = W3 + (size_t)yb * H2;
    const float* wj = W3 + (size_t)j * H2;
    const float* d2r = g_d2 + b * H2;
    const float* lmr = g_l2m + b * H2;
    float sa = 0.f, sbv = 0.f;
    for (int t = threadIdx.x; t < H2; t += 256) {
        float nu = (wy[t] - wj[t]) * d2r[t];
        g_nu2[(size_t)r * H2 + t] = nu;
        sa += fmaxf(-nu, 0.f) * lmr[t];
        sbv += nu * b2[t];
    }
    sAq[threadIdx.x] = sa; sBq[threadIdx.x] = sbv;
    __syncthreads();
    for (int o = 128; o > 0; o >>= 1) {
        if (threadIdx.x < o) {
            sAq[threadIdx.x] += sAq[threadIdx.x + o];
            sBq[threadIdx.x] += sBq[threadIdx.x + o];
        }
        __syncthreads();
    }
    if (threadIdx.x == 0) g_term[r] = (b3[yb] - b3[j]) + sBq[0] + sAq[0];
}

// ---------------- K5: nu1f = nu2 @ g_Ab[b]; fused final dots -------------------
__global__ void k_nu1f() {
    __shared__ float snu[NC][64];
    __shared__ float sp1[NC][4], sp2[NC][4];
    int b = blockIdx.y;
    int iblk = blockIdx.x;
    int i = iblk * 128 + threadIdx.x;
    int lane = threadIdx.x & 31, wrp = threadIdx.x >> 5;
    float acc[NC];
    #pragma unroll
    for (int j = 0; j < NC; j++) acc[j] = 0.f;
    for (int t0 = 0; t0 < H2; t0 += 64) {
        __syncthreads();
        for (int idx = threadIdx.x; idx < NC * 64; idx += 128)
            snu[idx >> 6][idx & 63] =
                g_nu2[(size_t)(b * NC + (idx >> 6)) * H2 + t0 + (idx & 63)];
        __syncthreads();
        for (int t = 0; t < 64; t++) {
            float w = __bfloat162float(g_Ab[((size_t)b * H2 + t0 + t) * H1 + i]);
            #pragma unroll
            for (int j = 0; j < NC; j++) acc[j] = fmaf(snu[j][t], w, acc[j]);
        }
    }
    float nom = g_nom1[b * H1 + i];
    float lm  = g_l1m[b * H1 + i];
    #pragma unroll
    for (int j = 0; j < NC; j++) {
        float v = acc[j];
        g_nu1fb[(size_t)(b * NC + j) * H1 + i] = __float2bfloat16(v);
        float p1 = v * nom;
        float p2 = fmaxf(-v, 0.f) * lm;
        p1 = warp_sum(p1); p2 = warp_sum(p2);
        if (lane == 0) { sp1[j][wrp] = p1; sp2[j][wrp] = p2; }
    }
    __syncthreads();
    if (threadIdx.x < NC) {
        int j = threadIdx.x;
        int r = b * NC + j;
        g_afp[iblk][r] = sp1[j][0] + sp1[j][1] + sp1[j][2] + sp1[j][3];
        g_crp[iblk][r] = sp2[j][0] + sp2[j][1] + sp2[j][2] + sp2[j][3];
    }
}

// ---------------- K7: output ---------------------------------------------------
__global__ void k_out(float* __restrict__ out) {
    int r = threadIdx.x;
    if (r < NROWS) {
        float Ef = 0.f, af = 0.f, cr = 0.f;
        #pragma unroll
        for (int c = 0; c < NT_TILES; c++) Ef += g_Efp[c][r];
        #pragma unroll
        for (int c = 0; c < NIBLK; c++) { af += g_afp[c][r]; cr += g_crp[c][r]; }
        out[r] = -(af + g_term[r] - EPSV * Ef + cr);
    }
}

// ---------------- launch --------------------------------------------------------
extern "C" void kernel_launch(void* const* d_in, const int* in_sizes, int n_in,
                              void* d_out, int out_size) {
    const float* x  = (const float*)d_in[0];
    const int*   y  = (const int*)  d_in[1];
    const float* W1 = (const float*)d_in[2];
    const float* b1 = (const float*)d_in[3];
    const float* W2 = (const float*)d_in[4];
    const float* b2 = (const float*)d_in[5];
    const float* W3 = (const float*)d_in[6];
    const float* b3 = (const float*)d_in[7];
    float* out = (float*)d_out;

    float* pE2;  cudaGetSymbolAddress((void**)&pE2, g_E2);
    float* pEfp; cudaGetSymbolAddress((void**)&pEfp, g_Efp);
    __nv_bfloat16* pAb;    cudaGetSymbolAddress((void**)&pAb, g_Ab);
    __nv_bfloat16* pnu1fb; cudaGetSymbolAddress((void**)&pnu1fb, g_nu1fb);

    const int SMEM = 4 * (ASTG + BSTG);   // 221184 (sred aliased into stage 0)
    cudaFuncSetAttribute(k_absgemm_mma, cudaFuncAttributeMaxDynamicSharedMemorySize, SMEM);

    k_prep<<<1408, 256>>>(W1);
    k_layer1<<<BATCH * H1 / 8, 256>>>(x, W1, b1);
    k_scaleA<<<16384, 256>>>(W2);
    k_absgemm_mma<<<dim3(4, 1, BATCH), 512, SMEM>>>(pAb, pE2, H2, NT_TILES, 0);   // profiled
    k_layer2<<<BATCH * H2 / 8, 256>>>(b2);
    k_nu2<<<NROWS, 256>>>(W3, b2, b3, y);
    k_nu1f<<<dim3(NIBLK, BATCH), 128>>>();
    k_absgemm_mma<<<dim3(2, NT_TILES, 1), 512, SMEM>>>(pnu1fb, pEfp, NROWS, 1, NROWS);
    k_out<<<1, 512>>>(out);
}

// round 17
// speedup vs baseline: 1.2181x; 1.0200x over previous
#include <cuda_runtime.h>
#include <cuda_bf16.h>
#include <cstdint>

#define BATCH 32
#define IN_F  784
#define H1    1024
#define H2    1024
#define NC    10
#define EPSV  0.1f
#define NROWS (BATCH * NC)   // 320
#define MROWS1 512           // padded rows for final GEMM (2 x 256)
#define NT_TILES 7           // 7*128 = 896 >= 784
#define SAS2 72              // halves per smem row for BK=64 (144B)
#define ASTG (256 * SAS2 * 2)   // 36864 B per A stage
#define BSTG (128 * SAS2 * 2)   // 18432 B per B stage
#define NIBLK 8              // i-blocks in k_nu1f

// ---------------- scratch (device globals) ----------------------------------
__device__ float g_r1[H1];
__device__ float g_nom1[BATCH * H1];
__device__ float g_d1[BATCH * H1];
__device__ float g_l1m[BATCH * H1];
__device__ float g_E2[BATCH * H2];
__device__ float g_d2[BATCH * H2];
__device__ float g_l2m[BATCH * H2];
__device__ float g_nu2[NROWS * H2];
__device__ float g_term[NROWS];
__device__ __nv_bfloat16 g_nu1fb[MROWS1 * H1];    // rows 320..511 zero
__device__ __nv_bfloat16 g_W1T[H1 * H1];          // W1^T bf16; rows >=784 zero
__device__ __nv_bfloat16 g_Ab[(size_t)BATCH * H2 * H1];  // W2 * d1[b] (64MB)
__device__ float g_Efp[NT_TILES][NROWS];
__device__ float g_afp[NIBLK][NROWS];
__device__ float g_crp[NIBLK][NROWS];

// ---------------- helpers ----------------------------------------------------
__device__ __forceinline__ uint32_t smem_u32(const void* p) {
    uint32_t a;
    asm("{ .reg .u64 t; cvta.to.shared.u64 t, %1; cvt.u32.u64 %0, t; }" : "=r"(a) : "l"(p));
    return a;
}
__device__ __forceinline__ void cp_async16(uint32_t saddr, const void* gaddr) {
    asm volatile("cp.async.cg.shared.global [%0], [%1], 16;" :: "r"(saddr), "l"(gaddr));
}
__device__ __forceinline__ void cp_commit() {
    asm volatile("cp.async.commit_group;" ::: "memory");
}
template <int N>
__device__ __forceinline__ void cp_wait() {
    asm volatile("cp.async.wait_group %0;" :: "n"(N) : "memory");
}
__device__ __forceinline__ void ldsm_x4(uint32_t& r0, uint32_t& r1, uint32_t& r2,
                                        uint32_t& r3, uint32_t addr) {
    asm volatile("ldmatrix.sync.aligned.m8n8.x4.shared.b16 {%0,%1,%2,%3}, [%4];"
                 : "=r"(r0), "=r"(r1), "=r"(r2), "=r"(r3) : "r"(addr));
}
__device__ __forceinline__ void mma16816(float* c, const uint32_t* a, uint32_t b0,
                                         uint32_t b1) {
    asm volatile(
        "mma.sync.aligned.m16n8k16.row.col.f32.bf16.bf16.f32 "
        "{%0,%1,%2,%3}, {%4,%5,%6,%7}, {%8,%9}, {%0,%1,%2,%3};"
        : "+f"(c[0]), "+f"(c[1]), "+f"(c[2]), "+f"(c[3])
        : "r"(a[0]), "r"(a[1]), "r"(a[2]), "r"(a[3]), "r"(b0), "r"(b1));
}
__device__ __forceinline__ float warp_sum(float v) {
    #pragma unroll
    for (int o = 16; o > 0; o >>= 1) v += __shfl_xor_sync(0xFFFFFFFFu, v, o);
    return v;
}
__device__ __forceinline__ void relu_coeffs(float zl, float zu, float& d, float& lm) {
    if (zl >= 0.f)      { d = 1.f; lm = 0.f; }
    else if (zu <= 0.f) { d = 0.f; lm = 0.f; }
    else                { d = zu / (zu - zl); lm = zl; }
}

// ---------------- K_prep: fused r1 + W1 transpose + zero pads -----------------
__global__ void k_prep(const float* __restrict__ W1) {
    int bx = blockIdx.x;
    if (bx < 800) {
        __shared__ float tile[32][33];
        int n0 = (bx % 25) * 32, i0 = (bx / 25) * 32;
        int tx = threadIdx.x & 31, ty = threadIdx.x >> 5;   // 32 x 8
        #pragma unroll
        for (int r = 0; r < 4; r++) {
            int i = i0 + ty + 8 * r, n = n0 + tx;
            tile[ty + 8 * r][tx] = (n < IN_F) ? W1[i * IN_F + n] : 0.f;
        }
        __syncthreads();
        #pragma unroll
        for (int r = 0; r < 4; r++) {
            int n = n0 + ty + 8 * r;
            if (n < IN_F)
                g_W1T[(size_t)n * H1 + i0 + tx] = __float2bfloat16(tile[tx][ty + 8 * r]);
        }
    } else if (bx < 928) {
        int gw = ((bx - 800) * 256 + threadIdx.x) >> 5, lane = threadIdx.x & 31;
        const float* row = W1 + gw * IN_F;
        float s = 0.f;
        for (int k = lane; k < IN_F; k += 32) s += fabsf(row[k]);
        s = warp_sum(s);
        if (lane == 0) g_r1[gw] = EPSV * s;
    } else {
        int idx = (bx - 928) * 256 + threadIdx.x;       // 480*256 = 122880
        uint32_t* w = (uint32_t*)g_W1T;
        w[IN_F * (H1 / 2) + idx] = 0u;                  // W1T rows 784..1023
        if (idx < (MROWS1 - NROWS) * (H1 / 2)) {        // 98304
            uint32_t* nb = (uint32_t*)g_nu1fb;
            nb[NROWS * (H1 / 2) + idx] = 0u;            // nu1fb rows 320..511
        }
    }
}

// ---------------- K1: layer-1 bounds ------------------------------------------
__global__ void k_layer1(const float* __restrict__ x, const float* __restrict__ W1,
                         const float* __restrict__ b1) {
    int gw = (blockIdx.x * blockDim.x + threadIdx.x) >> 5, lane = threadIdx.x & 31;
    int b = gw >> 10, j = gw & (H1 - 1);
    const float* xr = x + b * IN_F;
    const float* wr = W1 + j * IN_F;
    float s = 0.f;
    for (int k = lane; k < IN_F; k += 32) s += xr[k] * wr[k];
    s = warp_sum(s);
    if (lane == 0) {
        float nom = s + b1[j], r = g_r1[j], d, lm;
        relu_coeffs(nom - r, nom + r, d, lm);
        g_nom1[gw] = nom; g_d1[gw] = d; g_l1m[gw] = lm;
    }
}

// ---------------- A precompute: g_Ab = bf16(W2 * d1[b]) -----------------------
__global__ void k_scaleA(const float* __restrict__ W2) {
    size_t idx = ((size_t)blockIdx.x * 256 + threadIdx.x) * 8;    // 32M elems
    int b = (int)(idx >> 20);
    int i = (int)(idx & 1023);
    size_t wo = idx & 0xFFFFFu;
    float4 w0 = *(const float4*)(W2 + wo);
    float4 w1 = *(const float4*)(W2 + wo + 4);
    const float* dp = g_d1 + b * H1 + i;
    float4 e0 = *(const float4*)dp;
    float4 e1 = *(const float4*)(dp + 4);
    __nv_bfloat162 p0 = __floats2bfloat162_rn(w0.x * e0.x, w0.y * e0.y);
    __nv_bfloat162 p1 = __floats2bfloat162_rn(w0.z * e0.z, w0.w * e0.w);
    __nv_bfloat162 p2 = __floats2bfloat162_rn(w1.x * e1.x, w1.y * e1.y);
    __nv_bfloat162 p3 = __floats2bfloat162_rn(w1.z * e1.z, w1.w * e1.w);
    uint4 o;
    o.x = *(uint32_t*)&p0; o.y = *(uint32_t*)&p1;
    o.z = *(uint32_t*)&p2; o.w = *(uint32_t*)&p3;
    *(uint4*)(g_Ab + idx) = o;
}

// ---------------- tensor-core abs-row-sum GEMM --------------------------------
// BM=256, BN=128, 1024 thr (8x4 warps, warp tile m32n32), BK=64, 4 stages.
// 32 warps/SM -> occ 50% for latency hiding; acc 32 regs/thread.
// RAW rowsum: Eout[b*H2 + blockIdx.y*chunkStride + row] = sum_n |sum_i A[row,i]*B[n,i]|
__global__ void __launch_bounds__(1024, 1)
k_absgemm_mma(const __nv_bfloat16* __restrict__ Abase, float* __restrict__ Eout,
              int rowlimit, int ntPerCta, int chunkStride) {
    extern __shared__ char dsm[];
    __nv_bfloat16* sAp = (__nv_bfloat16*)dsm;
    __nv_bfloat16* sBp = sAp + 4 * 256 * SAS2;
    float* sred = (float*)dsm;                       // aliased after main loop

    const int tid = threadIdx.x, lane = tid & 31, wid = tid >> 5;
    const int warp_m = wid & 7, warp_n = wid >> 3;   // 8 x 4
    const int mtile = blockIdx.x, b = blockIdx.z;
    const int ntBase = blockIdx.y * ntPerCta;
    const __nv_bfloat16* A = Abase + ((size_t)b * H2 + mtile * 256) * H1;
    const __nv_bfloat16* B = g_W1T;

    const int aRow  = warp_m * 32 + (lane & 7) + ((lane >> 3) & 1) * 8;
    const int aColH = (lane >> 4) * 8;
    const int bRow  = warp_n * 32 + (lane & 7) + (lane >> 4) * 8;
    const int bColH = ((lane >> 3) & 1) * 8;

    const uint32_t sA0 = smem_u32(sAp);
    const uint32_t sB0 = smem_u32(sBp);

    // loaders (BK=64, 1024 thr): A 256x8 slots = 2048 -> 2/thread; B 128x8 = 1024 -> 1/thread
    const int alrow = tid >> 2, alq = (tid & 3) * 2;
    const int blrow = tid >> 3, blq = tid & 7;

    auto copy_stage = [&](int g, int buf) {
        int kt = g & 15, nt = ntBase + (g >> 4);
        int k0 = kt * 64;
        uint32_t Ao = sA0 + (uint32_t)buf * ASTG;
        uint32_t Bo = sB0 + (uint32_t)buf * BSTG;
        #pragma unroll
        for (int s = 0; s < 2; s++) {
            int q = alq + s;
            cp_async16(Ao + (alrow * SAS2 + q * 8) * 2,
                       A + (size_t)alrow * H1 + k0 + q * 8);
        }
        cp_async16(Bo + (blrow * SAS2 + blq * 8) * 2,
                   B + (size_t)(nt * 128 + blrow) * H1 + k0 + blq * 8);
    };

    const int total = ntPerCta * 16;
    copy_stage(0, 0); cp_commit();
    copy_stage(1, 1); cp_commit();
    copy_stage(2, 2); cp_commit();

    float rs[2][2];
    #pragma unroll
    for (int mi = 0; mi < 2; mi++) { rs[mi][0] = 0.f; rs[mi][1] = 0.f; }
    float acc[2][4][4];
    #pragma unroll
    for (int mi = 0; mi < 2; mi++)
        #pragma unroll
        for (int ni = 0; ni < 4; ni++)
            #pragma unroll
            for (int e = 0; e < 4; e++) acc[mi][ni][e] = 0.f;

    for (int g = 0; g < total; g++) {
        cp_wait<2>();
        __syncthreads();
        if (g + 3 < total) copy_stage(g + 3, (g + 3) & 3);
        cp_commit();

        int buf = g & 3;
        uint32_t aBase = sA0 + buf * ASTG;
        uint32_t bBase = sB0 + buf * BSTG;
        #pragma unroll
        for (int ks = 0; ks < 4; ks++) {
            uint32_t af[2][4];
            #pragma unroll
            for (int mi = 0; mi < 2; mi++)
                ldsm_x4(af[mi][0], af[mi][1], af[mi][2], af[mi][3],
                        aBase + ((aRow + mi * 16) * SAS2 + ks * 16 + aColH) * 2);
            uint32_t bf[2][4];
            #pragma unroll
            for (int np = 0; np < 2; np++)
                ldsm_x4(bf[np][0], bf[np][1], bf[np][2], bf[np][3],
                        bBase + ((bRow + np * 16) * SAS2 + ks * 16 + bColH) * 2);
            #pragma unroll
            for (int mi = 0; mi < 2; mi++)
                #pragma unroll
                for (int ni = 0; ni < 4; ni++)
                    mma16816(acc[mi][ni], af[mi],
                             bf[ni >> 1][(ni & 1) * 2], bf[ni >> 1][(ni & 1) * 2 + 1]);
        }

        if ((g & 15) == 15) {
            #pragma unroll
            for (int mi = 0; mi < 2; mi++)
                #pragma unroll
                for (int ni = 0; ni < 4; ni++) {
                    rs[mi][0] += fabsf(acc[mi][ni][0]) + fabsf(acc[mi][ni][1]);
                    rs[mi][1] += fabsf(acc[mi][ni][2]) + fabsf(acc[mi][ni][3]);
                    acc[mi][ni][0] = 0.f; acc[mi][ni][1] = 0.f;
                    acc[mi][ni][2] = 0.f; acc[mi][ni][3] = 0.f;
                }
        }
    }

    __syncthreads();   // stages dead; sred aliases stage memory
    #pragma unroll
    for (int mi = 0; mi < 2; mi++)
        #pragma unroll
        for (int h = 0; h < 2; h++) {
            float v = rs[mi][h];
            v += __shfl_xor_sync(0xFFFFFFFFu, v, 1);
            v += __shfl_xor_sync(0xFFFFFFFFu, v, 2);
            if ((lane & 3) == 0)
                sred[(warp_m * 32 + mi * 16 + (lane >> 2) + h * 8) * 4 + warp_n] = v;
        }
    __syncthreads();
    if (tid < 256) {
        float s = sred[tid * 4 + 0] + sred[tid * 4 + 1] + sred[tid * 4 + 2] + sred[tid * 4 + 3];
        int grow = mtile * 256 + tid;
        if (grow < rowlimit)
            Eout[(size_t)b * H2 + (size_t)blockIdx.y * chunkStride + grow] = s;
    }
}

// ---------------- K3: layer-2 bounds (reads bf16 g_Ab) -------------------------
__global__ void k_layer2(const float* __restrict__ b2) {
    int gw = (blockIdx.x * blockDim.x + threadIdx.x) >> 5, lane = threadIdx.x & 31;
    int b = gw >> 10, j = gw & (H2 - 1);
    const __nv_bfloat162* ab = (const __nv_bfloat162*)(g_Ab + ((size_t)b * H2 + j) * H1);
    const float2* nom2 = (const float2*)(g_nom1 + b * H1);
    const float2* lm2  = (const float2*)(g_l1m + b * H1);
    float s1 = 0.f, s2 = 0.f, s3 = 0.f;
    for (int i = lane; i < H1 / 2; i += 32) {
        float2 nu = __bfloat1622float2(ab[i]);
        float2 nm = nom2[i];
        float2 lm = lm2[i];
        s1 += nu.x * nm.x + nu.y * nm.y;
        s2 += fmaxf(-nu.x, 0.f) * lm.x + fmaxf(-nu.y, 0.f) * lm.y;
        s3 += fmaxf(nu.x, 0.f) * lm.x + fmaxf(nu.y, 0.f) * lm.y;
    }
    s1 = warp_sum(s1); s2 = warp_sum(s2); s3 = warp_sum(s3);
    if (lane == 0) {
        float A = s1 + b2[j];
        float E = EPSV * g_E2[gw];
        float d, lm;
        relu_coeffs(A - E + s2, A + E - s3, d, lm);
        g_d2[gw] = d; g_l2m[gw] = lm;
    }
}

// ---------------- K4: nu2 + bias/cross ----------------------------------------
__global__ void k_nu2(const float* __restrict__ W3, const float* __restrict__ b2,
                      const float* __restrict__ b3, const int* __restrict__ y) {
    __shared__ float sAq[256], sBq[256];
    int r = blockIdx.x, b = r / NC, j = r % NC;
    int yb = y[b];
    const float* wy = W3 + (size_t)yb * H2;
    const float* wj = W3 + (size_t)j * H2;
    const float* d2r = g_d2 + b * H2;
    const float* lmr = g_l2m + b * H2;
    float sa = 0.f, sbv = 0.f;
    for (int t = threadIdx.x; t < H2; t += 256) {
        float nu = (wy[t] - wj[t]) * d2r[t];
        g_nu2[(size_t)r * H2 + t] = nu;
        sa += fmaxf(-nu, 0.f) * lmr[t];
        sbv += nu * b2[t];
    }
    sAq[threadIdx.x] = sa; sBq[threadIdx.x] = sbv;
    __syncthreads();
    for (int o = 128; o > 0; o >>= 1) {
        if (threadIdx.x < o) {
            sAq[threadIdx.x] += sAq[threadIdx.x + o];
            sBq[threadIdx.x] += sBq[threadIdx.x + o];
        }
        __syncthreads();
    }
    if (threadIdx.x == 0) g_term[r] = (b3[yb] - b3[j]) + sBq[0] + sAq[0];
}

// ---------------- K5: nu1f = nu2 @ g_Ab[b]; fused final dots -------------------
__global__ void k_nu1f() {
    __shared__ float snu[NC][64];
    __shared__ float sp1[NC][4], sp2[NC][4];
    int b = blockIdx.y;
    int iblk = blockIdx.x;
    int i = iblk * 128 + threadIdx.x;
    int lane = threadIdx.x & 31, wrp = threadIdx.x >> 5;
    float acc[NC];
    #pragma unroll
    for (int j = 0; j < NC; j++) acc[j] = 0.f;
    for (int t0 = 0; t0 < H2; t0 += 64) {
        __syncthreads();
        for (int idx = threadIdx.x; idx < NC * 64; idx += 128)
            snu[idx >> 6][idx & 63] =
                g_nu2[(size_t)(b * NC + (idx >> 6)) * H2 + t0 + (idx & 63)];
        __syncthreads();
        for (int t = 0; t < 64; t++) {
            float w = __bfloat162float(g_Ab[((size_t)b * H2 + t0 + t) * H1 + i]);
            #pragma unroll
            for (int j = 0; j < NC; j++) acc[j] = fmaf(snu[j][t], w, acc[j]);
        }
    }
    float nom = g_nom1[b * H1 + i];
    float lm  = g_l1m[b * H1 + i];
    #pragma unroll
    for (int j = 0; j < NC; j++) {
        float v = acc[j];
        g_nu1fb[(size_t)(b * NC + j) * H1 + i] = __float2bfloat16(v);
        float p1 = v * nom;
        float p2 = fmaxf(-v, 0.f) * lm;
        p1 = warp_sum(p1); p2 = warp_sum(p2);
        if (lane == 0) { sp1[j][wrp] = p1; sp2[j][wrp] = p2; }
    }
    __syncthreads();
    if (threadIdx.x < NC) {
        int j = threadIdx.x;
        int r = b * NC + j;
        g_afp[iblk][r] = sp1[j][0] + sp1[j][1] + sp1[j][2] + sp1[j][3];
        g_crp[iblk][r] = sp2[j][0] + sp2[j][1] + sp2[j][2] + sp2[j][3];
    }
}

// ---------------- K7: output ---------------------------------------------------
__global__ void k_out(float* __restrict__ out) {
    int r = threadIdx.x;
    if (r < NROWS) {
        float Ef = 0.f, af = 0.f, cr = 0.f;
        #pragma unroll
        for (int c = 0; c < NT_TILES; c++) Ef += g_Efp[c][r];
        #pragma unroll
        for (int c = 0; c < NIBLK; c++) { af += g_afp[c][r]; cr += g_crp[c][r]; }
        out[r] = -(af + g_term[r] - EPSV * Ef + cr);
    }
}

// ---------------- launch --------------------------------------------------------
extern "C" void kernel_launch(void* const* d_in, const int* in_sizes, int n_in,
                              void* d_out, int out_size) {
    const float* x  = (const float*)d_in[0];
    const int*   y  = (const int*)  d_in[1];
    const float* W1 = (const float*)d_in[2];
    const float* b1 = (const float*)d_in[3];
    const float* W2 = (const float*)d_in[4];
    const float* b2 = (const float*)d_in[5];
    const float* W3 = (const float*)d_in[6];
    const float* b3 = (const float*)d_in[7];
    float* out = (float*)d_out;

    float* pE2;  cudaGetSymbolAddress((void**)&pE2, g_E2);
    float* pEfp; cudaGetSymbolAddress((void**)&pEfp, g_Efp);
    __nv_bfloat16* pAb;    cudaGetSymbolAddress((void**)&pAb, g_Ab);
    __nv_bfloat16* pnu1fb; cudaGetSymbolAddress((void**)&pnu1fb, g_nu1fb);

    const int SMEM = 4 * (ASTG + BSTG);   // 221184 (sred aliased into stage 0)
    cudaFuncSetAttribute(k_absgemm_mma, cudaFuncAttributeMaxDynamicSharedMemorySize, SMEM);

    k_prep<<<1408, 256>>>(W1);
    k_layer1<<<BATCH * H1 / 8, 256>>>(x, W1, b1);
    k_scaleA<<<16384, 256>>>(W2);
    k_absgemm_mma<<<dim3(4, 1, BATCH), 1024, SMEM>>>(pAb, pE2, H2, NT_TILES, 0);   // profiled
    k_layer2<<<BATCH * H2 / 8, 256>>>(b2);
    k_nu2<<<NROWS, 256>>>(W3, b2, b3, y);
    k_nu1f<<<dim3(NIBLK, BATCH), 128>>>();
    k_absgemm_mma<<<dim3(2, NT_TILES, 1), 1024, SMEM>>>(pnu1fb, pEfp, NROWS, 1, NROWS);
    k_out<<<1, 512>>>(out);
}